// round 11
// baseline (speedup 1.0000x reference)
#include <cuda_runtime.h>
#include <cuda_bf16.h>
#include <math.h>
#include <stdint.h>

// ---------------- problem constants ----------------
#define NB 2
#define NN 16384
#define CIN 64
#define NP 2048
#define NS 32
#define CD 256
#define KP1 80                  // 3+64=67 padded to 80
#define NROWS (NB*NP*NS)        // 131072
#define FPS_T 1024
#define FPS_SLOTS (NN / FPS_T)  // 16
#define FPS_SMEM (NN * 12)      // float2 xy + float z

// ---------------- scratch (device globals; no allocation allowed) ----------------
__device__ alignas(256) int   g_samp[NB * NP];
__device__ alignas(256) float g_newxyz[NB * NP * 3];
__device__ alignas(256) int   g_nn[NROWS];
__device__ alignas(256) float g_featT[(size_t)NB * NN * CIN];
__device__ alignas(256) float g_Wp1[64 * KP1];
__device__ alignas(256) float g_G[(size_t)NROWS * KP1];
__device__ alignas(256) float g_H1[(size_t)NROWS * 64];
__device__ alignas(256) float g_H2[(size_t)NROWS * 128];
__device__ alignas(256) float g_H3[(size_t)NROWS * 256];
__device__ alignas(256) float g_xh[(size_t)NB * NP * CD];   // (b,p,c)
__device__ alignas(256) float g_qt[(size_t)NB * CD * CD];
__device__ alignas(256) float g_kt[(size_t)NB * CD * CD];
__device__ alignas(256) float g_aff[(size_t)NB * CD * CD];
__device__ alignas(256) float g_s[NB * CD];
__device__ alignas(256) float g_e[NB * CD];

// ================= FPS =================
// One CTA per batch. Points cached in dynamic SMEM. Exact jnp.argmax
// (first-index tie-break) via (val, min-global-index) reductions.
extern __shared__ unsigned char fps_sm[];

__global__ void __launch_bounds__(FPS_T, 1) fps_kernel(const float* __restrict__ xyz) {
    float2* xy = (float2*)fps_sm;
    float*  zz = (float*)(fps_sm + (size_t)NN * sizeof(float2));
    __shared__ float sv[32];
    __shared__ int   si[32];
    __shared__ int   scur;

    int b = blockIdx.x, t = threadIdx.x;
    const float* xb = xyz + (size_t)b * NN * 3;
    float mind[FPS_SLOTS];
#pragma unroll
    for (int s = 0; s < FPS_SLOTS; s++) {
        int p = t + s * FPS_T;
        xy[p] = make_float2(xb[p * 3 + 0], xb[p * 3 + 1]);
        zz[p] = xb[p * 3 + 2];
        mind[s] = 3.4e38f;
    }
    if (t == 0) { g_samp[b * NP + 0] = 0; scur = 0; }
    __syncthreads();

    int lane = t & 31, wid = t >> 5;
    for (int i = 1; i < NP; i++) {
        int cur = scur;
        float2 cxy = xy[cur];
        float  cz  = zz[cur];
        float vmax = -1.0f; int gidx = 0;
#pragma unroll
        for (int s = 0; s < FPS_SLOTS; s++) {
            int p = t + s * FPS_T;
            float2 a = xy[p];
            float dx = a.x - cxy.x, dy = a.y - cxy.y, dz = zz[p] - cz;
            float d = dx * dx + dy * dy + dz * dz;
            float m = fminf(mind[s], d);
            mind[s] = m;
            if (m > vmax) { vmax = m; gidx = p; }   // ascending p -> first-index ties
        }
#pragma unroll
        for (int o = 16; o; o >>= 1) {
            float v2 = __shfl_xor_sync(0xffffffffu, vmax, o);
            int   i2 = __shfl_xor_sync(0xffffffffu, gidx, o);
            if (v2 > vmax || (v2 == vmax && i2 < gidx)) { vmax = v2; gidx = i2; }
        }
        if (lane == 0) { sv[wid] = vmax; si[wid] = gidx; }
        __syncthreads();
        if (wid == 0) {
            float v = sv[lane]; int gi = si[lane];
#pragma unroll
            for (int o = 16; o; o >>= 1) {
                float v2 = __shfl_xor_sync(0xffffffffu, v, o);
                int   i2 = __shfl_xor_sync(0xffffffffu, gi, o);
                if (v2 > v || (v2 == v && i2 < gi)) { v = v2; gi = i2; }
            }
            if (lane == 0) { scur = gi; g_samp[b * NP + i] = gi; }
        }
        __syncthreads();
    }
}

// ================= gather new_xyz (also writes first section of d_out) ============
__global__ void gather_new_kernel(const float* __restrict__ xyz, float* __restrict__ out) {
    int i = blockIdx.x * blockDim.x + threadIdx.x;
    if (i >= NB * NP * 3) return;
    int bp = i / 3, k = i - bp * 3;
    int b = bp / NP;
    int idx = g_samp[bp];
    float v = xyz[((size_t)b * NN + idx) * 3 + k];
    out[i] = v;
    g_newxyz[i] = v;
}

// ================= ball query: first NS in-range by ascending index, pad w/ first hit
__global__ void ball_query_kernel(const float* __restrict__ xyz) {
    int gw = (blockIdx.x * blockDim.x + threadIdx.x) >> 5;
    int lane = threadIdx.x & 31;
    if (gw >= NB * NP) return;
    int b = gw / NP;
    float cx = g_newxyz[gw * 3 + 0], cy = g_newxyz[gw * 3 + 1], cz = g_newxyz[gw * 3 + 2];
    const float* xb = xyz + (size_t)b * NN * 3;
    int base = gw * NS;
    int cnt = 0, first = -1;
    const float rr = 0.8f * 0.8f;
    for (int c0 = 0; c0 < NN; c0 += 32) {
        int j = c0 + lane;
        float dx = cx - xb[j * 3 + 0];
        float dy = cy - xb[j * 3 + 1];
        float dz = cz - xb[j * 3 + 2];
        float d = dx * dx + dy * dy + dz * dz;
        bool in = d < rr;
        unsigned m = __ballot_sync(0xffffffffu, in);
        if (first < 0 && m) first = c0 + (__ffs(m) - 1);
        if (in) {
            int pos = cnt + __popc(m & ((1u << lane) - 1u));
            if (pos < NS) g_nn[base + pos] = j;
        }
        cnt += __popc(m);
        if (cnt >= NS) break;
    }
    if (cnt < NS) {
        for (int k = cnt + lane; k < NS; k += 32) g_nn[base + k] = first;
    }
}

// ================= transpose features (B,C,N) -> (B,N,C) ==================
__global__ void transpose_feat_kernel(const float* __restrict__ f) {
    __shared__ float tile[32][33];
    int b = blockIdx.z;
    int n0 = blockIdx.x * 32, c0 = blockIdx.y * 32;
#pragma unroll
    for (int r = 0; r < 4; r++) {
        int c = c0 + threadIdx.y + r * 8;
        tile[threadIdx.y + r * 8][threadIdx.x] =
            f[((size_t)b * CIN + c) * NN + n0 + threadIdx.x];
    }
    __syncthreads();
#pragma unroll
    for (int r = 0; r < 4; r++) {
        int n = n0 + threadIdx.y + r * 8;
        g_featT[((size_t)b * NN + n) * CIN + c0 + threadIdx.x] =
            tile[threadIdx.x][threadIdx.y + r * 8];
    }
}

// ================= pad W1 (64x67) -> (64x80) ==================
__global__ void pad_w1_kernel(const float* __restrict__ W1) {
    int o = blockIdx.x, k = threadIdx.x;
    g_Wp1[o * KP1 + k] = (k < 67) ? W1[o * 67 + k] : 0.0f;
}

// ================= build grouped matrix G (NROWS x 80) ==================
__global__ void build_g_kernel(const float* __restrict__ xyz) {
    int row = blockIdx.x;
    int k = threadIdx.x;            // 0..79
    int b = row / (NP * NS);
    int rem = row - b * (NP * NS);
    int p = rem / NS;
    int nn = g_nn[row];
    float v = 0.0f;
    if (k < 3)       v = xyz[((size_t)b * NN + nn) * 3 + k] - g_newxyz[(b * NP + p) * 3 + k];
    else if (k < 67) v = g_featT[((size_t)b * NN + nn) * CIN + (k - 3)];
    g_G[(size_t)row * KP1 + k] = v;
}

// ================= GEMM + BN(eval) + ReLU ==================
// C[m,n] = relu( (sum_k A[m,k]*W[n,k]) * g[n]/sqrt(1+eps) + b[n] )
template<int LAYER>
__global__ void __launch_bounds__(256) gemm_bn_relu(const float* __restrict__ W,
                                                    const float* __restrict__ gs,
                                                    const float* __restrict__ bt) {
    constexpr int K = (LAYER == 1) ? KP1 : ((LAYER == 2) ? 64 : 128);
    constexpr int N = (LAYER == 1) ? 64 : ((LAYER == 2) ? 128 : 256);
    const float* A = (LAYER == 1) ? (const float*)g_G
                   : (LAYER == 2) ? (const float*)g_H1 : (const float*)g_H2;
    float* C = (LAYER == 1) ? (float*)g_H1
             : (LAYER == 2) ? (float*)g_H2 : (float*)g_H3;
    const float* Wp = (LAYER == 1) ? (const float*)g_Wp1 : W;

    __shared__ float As[16][65];
    __shared__ float Ws[16][65];
    int tid = threadIdx.x;
    int tx = tid & 15, ty = tid >> 4;
    int m0 = blockIdx.x * 64, n0 = blockIdx.y * 64;
    int lm = tid >> 2, lk = (tid & 3) * 4;
    const float* Ag = A  + (size_t)(m0 + lm) * K + lk;
    const float* Wg = Wp + (size_t)(n0 + lm) * K + lk;
    float acc[4][4] = {};

    for (int kt = 0; kt < K; kt += 16) {
        float4 av = *(const float4*)(Ag + kt);
        float4 wv = *(const float4*)(Wg + kt);
        As[lk + 0][lm] = av.x; As[lk + 1][lm] = av.y; As[lk + 2][lm] = av.z; As[lk + 3][lm] = av.w;
        Ws[lk + 0][lm] = wv.x; Ws[lk + 1][lm] = wv.y; Ws[lk + 2][lm] = wv.z; Ws[lk + 3][lm] = wv.w;
        __syncthreads();
#pragma unroll
        for (int k = 0; k < 16; k++) {
            float a[4], bb[4];
#pragma unroll
            for (int i2 = 0; i2 < 4; i2++) a[i2] = As[k][ty * 4 + i2];
#pragma unroll
            for (int j = 0; j < 4; j++) bb[j] = Ws[k][tx * 4 + j];
#pragma unroll
            for (int i2 = 0; i2 < 4; i2++)
#pragma unroll
                for (int j = 0; j < 4; j++) acc[i2][j] = fmaf(a[i2], bb[j], acc[i2][j]);
        }
        __syncthreads();
    }
#pragma unroll
    for (int j = 0; j < 4; j++) {
        int n = n0 + tx * 4 + j;
        float s = gs[n] / sqrtf(1.0f + 1e-5f);
        float bb = bt[n];
#pragma unroll
        for (int i2 = 0; i2 < 4; i2++) {
            int m = m0 + ty * 4 + i2;
            C[(size_t)m * N + n] = fmaxf(fmaf(acc[i2][j], s, bb), 0.0f);
        }
    }
}

// ================= maxpool over NS samples -> xh (b,p,c) ==================
__global__ void maxpool_kernel() {
    int c = threadIdx.x;            // 256
    int bp = blockIdx.x;            // NB*NP
    const float* base = g_H3 + (size_t)bp * NS * CD + c;
    float m = base[0];
#pragma unroll
    for (int s = 1; s < NS; s++) m = fmaxf(m, base[(size_t)s * CD]);
    g_xh[(size_t)bp * CD + c] = m;
}

// ================= attention path (gated on alpha != 0) ==================
__global__ void squeeze_kernel(const float* __restrict__ alpha) {
    if (alpha[0] == 0.0f) return;
    int c = threadIdx.x, b = blockIdx.x;
    float m = -3.4e38f;
    for (int p = 0; p < NP; p++)
        m = fmaxf(m, g_xh[((size_t)b * NP + p) * CD + c]);
    g_s[b * CD + c] = m;
}

__global__ void excite_kernel(const float* __restrict__ We1, const float* __restrict__ We2,
                              const float* __restrict__ alpha) {
    if (alpha[0] == 0.0f) return;
    int b = blockIdx.x, t = threadIdx.x;
    __shared__ float h[32];
    if (t < 32) {
        float a = 0.0f;
        for (int i = 0; i < CD; i++) a += We1[t * CD + i] * g_s[b * CD + i];
        h[t] = fmaxf(a, 0.0f);
    }
    __syncthreads();
    float a = 0.0f;
    for (int j = 0; j < 32; j++) a += We2[t * 32 + j] * h[j];
    g_e[b * CD + t] = 1.0f / (1.0f + expf(-a));
}

__global__ void qk_kernel(const float* __restrict__ Wq, const float* __restrict__ gq,
                          const float* __restrict__ bq, const float* __restrict__ Wk,
                          const float* __restrict__ gk, const float* __restrict__ bk,
                          const float* __restrict__ alpha) {
    if (alpha[0] == 0.0f) return;
    int c = threadIdx.x, o = blockIdx.x, b = blockIdx.y, which = blockIdx.z;
    const float* W  = which ? Wk : Wq;
    const float* g  = which ? gk : gq;
    const float* bt = which ? bk : bq;
    float acc = 0.0f;
    const float* xb = g_xh + (size_t)b * NP * CD + c;
    const float* wr = W + (size_t)o * NP;
    for (int p = 0; p < NP; p++) acc += wr[p] * xb[(size_t)p * CD];
    float s = g[o] / sqrtf(1.0f + 1e-5f);
    float v = fmaxf(acc * s + bt[o], 0.0f);
    float* dst = which ? g_kt : g_qt;
    dst[((size_t)b * CD + o) * CD + c] = v;
}

__global__ void sim_softmax_kernel(const float* __restrict__ alpha) {
    if (alpha[0] == 0.0f) return;
    int c = blockIdx.x, b = blockIdx.y, d = threadIdx.x;
    __shared__ float sb[32];
    int lane = d & 31, wid = d >> 5;
    const float* kb = g_kt + (size_t)b * CD * CD;
    const float* qb = g_qt + (size_t)b * CD * CD;
    float sim = 0.0f;
    for (int q = 0; q < CD; q++) sim += kb[q * CD + c] * qb[q * CD + d];
    // softmax(rowmax - sim) == exp(rowmin - sim)/sum(exp(rowmin - sim))
    float mn = sim;
#pragma unroll
    for (int o = 16; o; o >>= 1) mn = fminf(mn, __shfl_xor_sync(0xffffffffu, mn, o));
    if (lane == 0) sb[wid] = mn;
    __syncthreads();
    float Mn = sb[0];
    for (int w = 1; w < 8; w++) Mn = fminf(Mn, sb[w]);
    __syncthreads();
    float num = expf(Mn - sim);
    float sm = num;
#pragma unroll
    for (int o = 16; o; o >>= 1) sm += __shfl_xor_sync(0xffffffffu, sm, o);
    if (lane == 0) sb[wid] = sm;
    __syncthreads();
    float S = 0.0f;
    for (int w = 0; w < 8; w++) S += sb[w];
    g_aff[((size_t)b * CD + c) * CD + d] = num / S;
}

// ================= final write: out[b,c,p] = alpha*(aff@v)[c,p] + x[c,p] ========
__global__ void final_write_kernel(float* __restrict__ out, const float* __restrict__ alpha) {
    int p = blockIdx.x * blockDim.x + threadIdx.x;
    int c = blockIdx.y, b = blockIdx.z;
    float a = alpha[0];
    float base = g_xh[((size_t)b * NP + p) * CD + c];
    float res = base;
    if (a != 0.0f) {
        const float* affr = g_aff + ((size_t)b * CD + c) * CD;
        const float* xhp  = g_xh + ((size_t)b * NP + p) * CD;
        const float* eb   = g_e + b * CD;
        float acc = 0.0f;
        for (int d = 0; d < CD; d++) acc += affr[d] * xhp[d] * eb[d];
        res = a * acc + base;
    }
    out[NB * NP * 3 + ((size_t)b * CD + c) * NP + p] = res;
}

// ================= host launcher ==================
extern "C" void kernel_launch(void* const* d_in, const int* in_sizes, int n_in,
                              void* d_out, int out_size) {
    const float* xyz  = (const float*)d_in[0];
    const float* feat = (const float*)d_in[1];
    const float* W1 = (const float*)d_in[2];
    const float* g1 = (const float*)d_in[3];
    const float* b1 = (const float*)d_in[4];
    const float* W2 = (const float*)d_in[5];
    const float* g2 = (const float*)d_in[6];
    const float* b2 = (const float*)d_in[7];
    const float* W3 = (const float*)d_in[8];
    const float* g3 = (const float*)d_in[9];
    const float* b3 = (const float*)d_in[10];
    const float* Wq = (const float*)d_in[11];
    const float* gq = (const float*)d_in[12];
    const float* bq = (const float*)d_in[13];
    const float* Wk = (const float*)d_in[14];
    const float* gk = (const float*)d_in[15];
    const float* bk = (const float*)d_in[16];
    const float* We1 = (const float*)d_in[17];
    const float* We2 = (const float*)d_in[18];
    const float* alpha = (const float*)d_in[19];
    float* out = (float*)d_out;

    cudaFuncSetAttribute(fps_kernel, cudaFuncAttributeMaxDynamicSharedMemorySize, FPS_SMEM);

    fps_kernel<<<NB, FPS_T, FPS_SMEM>>>(xyz);
    gather_new_kernel<<<(NB * NP * 3 + 255) / 256, 256>>>(xyz, out);
    ball_query_kernel<<<(NB * NP) / 8, 256>>>(xyz);
    transpose_feat_kernel<<<dim3(NN / 32, CIN / 32, NB), dim3(32, 8)>>>(feat);
    pad_w1_kernel<<<64, KP1>>>(W1);
    build_g_kernel<<<NROWS, KP1>>>(xyz);
    gemm_bn_relu<1><<<dim3(NROWS / 64, 1), 256>>>(W1, g1, b1);
    gemm_bn_relu<2><<<dim3(NROWS / 64, 2), 256>>>(W2, g2, b2);
    gemm_bn_relu<3><<<dim3(NROWS / 64, 4), 256>>>(W3, g3, b3);
    maxpool_kernel<<<NB * NP, CD>>>();
    // attention path (device-gated on alpha[0] != 0; alpha==0 in this dataset)
    squeeze_kernel<<<NB, CD>>>(alpha);
    excite_kernel<<<NB, CD>>>(We1, We2, alpha);
    qk_kernel<<<dim3(CD, NB, 2), CD>>>(Wq, gq, bq, Wk, gk, bk, alpha);
    sim_softmax_kernel<<<dim3(CD, NB), CD>>>(alpha);
    final_write_kernel<<<dim3(NP / 256, CD, NB), 256>>>(out, alpha);
}

// round 12
// speedup vs baseline: 1.4084x; 1.4084x over previous
#include <cuda_runtime.h>
#include <cuda_bf16.h>
#include <cooperative_groups.h>
#include <math.h>
#include <stdint.h>

namespace cg = cooperative_groups;

// ---------------- problem constants ----------------
#define NB 2
#define NN 16384
#define CIN 64
#define NP 2048
#define NS 32
#define CD 256
#define KP1 80                  // 3+64=67 padded to 80
#define NROWS (NB*NP*NS)        // 131072

// FPS cluster config
#define FT 512                  // threads per FPS CTA
#define CLS 8                   // cluster size (CTAs per batch)
#define SHARD (NN / CLS)        // 2048 points owned per CTA
#define SLOTS (SHARD / FT)      // 4 slots per thread
#define FPS_SMEM (NN * 12)      // full copy: float2 xy + float z = 196608 B

// ---------------- scratch (device globals; no allocation allowed) ----------------
__device__ alignas(256) int   g_samp[NB * NP];
__device__ alignas(256) float g_newxyz[NB * NP * 3];
__device__ alignas(256) int   g_nn[NROWS];
__device__ alignas(256) float g_featT[(size_t)NB * NN * CIN];
__device__ alignas(256) float g_Wp1[64 * KP1];
__device__ alignas(256) float g_G[(size_t)NROWS * KP1];
__device__ alignas(256) float g_H1[(size_t)NROWS * 64];
__device__ alignas(256) float g_H2[(size_t)NROWS * 128];
__device__ alignas(256) float g_H3[(size_t)NROWS * 256];
__device__ alignas(256) float g_xh[(size_t)NB * NP * CD];   // (b,p,c)
__device__ alignas(256) float g_qt[(size_t)NB * CD * CD];
__device__ alignas(256) float g_kt[(size_t)NB * CD * CD];
__device__ alignas(256) float g_aff[(size_t)NB * CD * CD];
__device__ alignas(256) float g_s[NB * CD];
__device__ alignas(256) float g_e[NB * CD];

// ================= FPS (cluster-distributed) =================
// 8 CTAs per batch in one cluster. Each CTA keeps a FULL smem copy of the
// points (so winner coords are always local) but updates min-dist only for
// its 2048-point shard. Per iteration, each CTA reduces its shard to one
// packed 64-bit key (dist_bits<<32 | ~index): max over keys == max dist,
// ties broken toward the SMALLEST index (exact jnp.argmax semantics).
// Cross-CTA: write own candidate -> cluster.sync -> warp0 reads 8 peer keys
// via DSMEM -> broadcast winner index. Double-buffered candidate slot makes
// one cluster.sync per iteration sufficient.
extern __shared__ unsigned char fps_sm[];

__global__ void __cluster_dims__(CLS, 1, 1) __launch_bounds__(FT, 1)
fps_cluster_kernel(const float* __restrict__ xyz) {
    float2* xy = (float2*)fps_sm;
    float*  zz = (float*)(fps_sm + (size_t)NN * sizeof(float2));
    __shared__ unsigned long long swarp[FT / 32];
    __shared__ unsigned long long cand[2];
    __shared__ int s_cur;

    cg::cluster_group cluster = cg::this_cluster();
    const unsigned rank = cluster.block_rank();
    const int b = blockIdx.x / CLS;
    const int t = threadIdx.x;
    const int lane = t & 31, wid = t >> 5;
    const int base = rank * SHARD;

    // full local copy of this batch's points
    const float* xb = xyz + (size_t)b * NN * 3;
    for (int p = t; p < NN; p += FT) {
        xy[p] = make_float2(xb[p * 3 + 0], xb[p * 3 + 1]);
        zz[p] = xb[p * 3 + 2];
    }
    float mind[SLOTS];
#pragma unroll
    for (int s = 0; s < SLOTS; s++) mind[s] = 3.4e38f;
    if (t == 0) {
        s_cur = 0;
        if (rank == 0) g_samp[b * NP + 0] = 0;
    }
    __syncthreads();

    int cur = 0;
    for (int i = 1; i < NP; i++) {
        float2 cxy = xy[cur];
        float  cz  = zz[cur];
        unsigned long long best = 0ull;
#pragma unroll
        for (int s = 0; s < SLOTS; s++) {
            int p = base + t + s * FT;
            float2 a = xy[p];
            float dx = a.x - cxy.x, dy = a.y - cxy.y, dz = zz[p] - cz;
            float d = dx * dx + dy * dy + dz * dz;     // identical expr to R11
            float m = fminf(mind[s], d);
            mind[s] = m;
            unsigned long long key =
                ((unsigned long long)__float_as_uint(m) << 32) | (unsigned)(~p);
            best = (key > best) ? key : best;
        }
        // warp reduce (max)
#pragma unroll
        for (int o = 16; o; o >>= 1) {
            unsigned long long v = __shfl_xor_sync(0xffffffffu, best, o);
            best = (v > best) ? v : best;
        }
        if (lane == 0) swarp[wid] = best;
        __syncthreads();
        if (wid == 0) {
            unsigned long long v = (lane < FT / 32) ? swarp[lane] : 0ull;
#pragma unroll
            for (int o = 8; o; o >>= 1) {
                unsigned long long v2 = __shfl_xor_sync(0xffffffffu, v, o);
                v = (v2 > v) ? v2 : v;
            }
            if (lane == 0) cand[i & 1] = v;
        }
        cluster.sync();   // all threads: publishes cand, acts as block barrier
        if (wid == 0) {
            unsigned long long v = 0ull;
            if (lane < CLS) {
                const unsigned long long* pc =
                    cluster.map_shared_rank((const unsigned long long*)&cand[i & 1], lane);
                v = *pc;
            }
#pragma unroll
            for (int o = 4; o; o >>= 1) {
                unsigned long long v2 = __shfl_xor_sync(0xffffffffu, v, o);
                v = (v2 > v) ? v2 : v;
            }
            if (lane == 0) {
                int widx = (int)(~(unsigned)v);
                s_cur = widx;
                if (rank == 0) g_samp[b * NP + i] = widx;
            }
        }
        __syncthreads();
        cur = s_cur;
    }
}

// ================= gather new_xyz (also writes first section of d_out) ============
__global__ void gather_new_kernel(const float* __restrict__ xyz, float* __restrict__ out) {
    int i = blockIdx.x * blockDim.x + threadIdx.x;
    if (i >= NB * NP * 3) return;
    int bp = i / 3, k = i - bp * 3;
    int b = bp / NP;
    int idx = g_samp[bp];
    float v = xyz[((size_t)b * NN + idx) * 3 + k];
    out[i] = v;
    g_newxyz[i] = v;
}

// ================= ball query: first NS in-range by ascending index, pad w/ first hit
__global__ void ball_query_kernel(const float* __restrict__ xyz) {
    int gw = (blockIdx.x * blockDim.x + threadIdx.x) >> 5;
    int lane = threadIdx.x & 31;
    if (gw >= NB * NP) return;
    int b = gw / NP;
    float cx = g_newxyz[gw * 3 + 0], cy = g_newxyz[gw * 3 + 1], cz = g_newxyz[gw * 3 + 2];
    const float* xb = xyz + (size_t)b * NN * 3;
    int base = gw * NS;
    int cnt = 0, first = -1;
    const float rr = 0.8f * 0.8f;
    for (int c0 = 0; c0 < NN; c0 += 32) {
        int j = c0 + lane;
        float dx = cx - xb[j * 3 + 0];
        float dy = cy - xb[j * 3 + 1];
        float dz = cz - xb[j * 3 + 2];
        float d = dx * dx + dy * dy + dz * dz;
        bool in = d < rr;
        unsigned m = __ballot_sync(0xffffffffu, in);
        if (first < 0 && m) first = c0 + (__ffs(m) - 1);
        if (in) {
            int pos = cnt + __popc(m & ((1u << lane) - 1u));
            if (pos < NS) g_nn[base + pos] = j;
        }
        cnt += __popc(m);
        if (cnt >= NS) break;
    }
    if (cnt < NS) {
        for (int k = cnt + lane; k < NS; k += 32) g_nn[base + k] = first;
    }
}

// ================= transpose features (B,C,N) -> (B,N,C) ==================
__global__ void transpose_feat_kernel(const float* __restrict__ f) {
    __shared__ float tile[32][33];
    int b = blockIdx.z;
    int n0 = blockIdx.x * 32, c0 = blockIdx.y * 32;
#pragma unroll
    for (int r = 0; r < 4; r++) {
        int c = c0 + threadIdx.y + r * 8;
        tile[threadIdx.y + r * 8][threadIdx.x] =
            f[((size_t)b * CIN + c) * NN + n0 + threadIdx.x];
    }
    __syncthreads();
#pragma unroll
    for (int r = 0; r < 4; r++) {
        int n = n0 + threadIdx.y + r * 8;
        g_featT[((size_t)b * NN + n) * CIN + c0 + threadIdx.x] =
            tile[threadIdx.x][threadIdx.y + r * 8];
    }
}

// ================= pad W1 (64x67) -> (64x80) ==================
__global__ void pad_w1_kernel(const float* __restrict__ W1) {
    int o = blockIdx.x, k = threadIdx.x;
    g_Wp1[o * KP1 + k] = (k < 67) ? W1[o * 67 + k] : 0.0f;
}

// ================= build grouped matrix G (NROWS x 80) ==================
__global__ void build_g_kernel(const float* __restrict__ xyz) {
    int row = blockIdx.x;
    int k = threadIdx.x;            // 0..79
    int b = row / (NP * NS);
    int rem = row - b * (NP * NS);
    int p = rem / NS;
    int nn = g_nn[row];
    float v = 0.0f;
    if (k < 3)       v = xyz[((size_t)b * NN + nn) * 3 + k] - g_newxyz[(b * NP + p) * 3 + k];
    else if (k < 67) v = g_featT[((size_t)b * NN + nn) * CIN + (k - 3)];
    g_G[(size_t)row * KP1 + k] = v;
}

// ================= GEMM + BN(eval) + ReLU ==================
// C[m,n] = relu( (sum_k A[m,k]*W[n,k]) * g[n]/sqrt(1+eps) + b[n] )
template<int LAYER>
__global__ void __launch_bounds__(256) gemm_bn_relu(const float* __restrict__ W,
                                                    const float* __restrict__ gs,
                                                    const float* __restrict__ bt) {
    constexpr int K = (LAYER == 1) ? KP1 : ((LAYER == 2) ? 64 : 128);
    constexpr int N = (LAYER == 1) ? 64 : ((LAYER == 2) ? 128 : 256);
    const float* A = (LAYER == 1) ? (const float*)g_G
                   : (LAYER == 2) ? (const float*)g_H1 : (const float*)g_H2;
    float* C = (LAYER == 1) ? (float*)g_H1
             : (LAYER == 2) ? (float*)g_H2 : (float*)g_H3;
    const float* Wp = (LAYER == 1) ? (const float*)g_Wp1 : W;

    __shared__ float As[16][65];
    __shared__ float Ws[16][65];
    int tid = threadIdx.x;
    int tx = tid & 15, ty = tid >> 4;
    int m0 = blockIdx.x * 64, n0 = blockIdx.y * 64;
    int lm = tid >> 2, lk = (tid & 3) * 4;
    const float* Ag = A  + (size_t)(m0 + lm) * K + lk;
    const float* Wg = Wp + (size_t)(n0 + lm) * K + lk;
    float acc[4][4] = {};

    for (int kt = 0; kt < K; kt += 16) {
        float4 av = *(const float4*)(Ag + kt);
        float4 wv = *(const float4*)(Wg + kt);
        As[lk + 0][lm] = av.x; As[lk + 1][lm] = av.y; As[lk + 2][lm] = av.z; As[lk + 3][lm] = av.w;
        Ws[lk + 0][lm] = wv.x; Ws[lk + 1][lm] = wv.y; Ws[lk + 2][lm] = wv.z; Ws[lk + 3][lm] = wv.w;
        __syncthreads();
#pragma unroll
        for (int k = 0; k < 16; k++) {
            float a[4], bb[4];
#pragma unroll
            for (int i2 = 0; i2 < 4; i2++) a[i2] = As[k][ty * 4 + i2];
#pragma unroll
            for (int j = 0; j < 4; j++) bb[j] = Ws[k][tx * 4 + j];
#pragma unroll
            for (int i2 = 0; i2 < 4; i2++)
#pragma unroll
                for (int j = 0; j < 4; j++) acc[i2][j] = fmaf(a[i2], bb[j], acc[i2][j]);
        }
        __syncthreads();
    }
#pragma unroll
    for (int j = 0; j < 4; j++) {
        int n = n0 + tx * 4 + j;
        float s = gs[n] / sqrtf(1.0f + 1e-5f);
        float bb = bt[n];
#pragma unroll
        for (int i2 = 0; i2 < 4; i2++) {
            int m = m0 + ty * 4 + i2;
            C[(size_t)m * N + n] = fmaxf(fmaf(acc[i2][j], s, bb), 0.0f);
        }
    }
}

// ================= maxpool over NS samples -> xh (b,p,c) ==================
__global__ void maxpool_kernel() {
    int c = threadIdx.x;            // 256
    int bp = blockIdx.x;            // NB*NP
    const float* base = g_H3 + (size_t)bp * NS * CD + c;
    float m = base[0];
#pragma unroll
    for (int s = 1; s < NS; s++) m = fmaxf(m, base[(size_t)s * CD]);
    g_xh[(size_t)bp * CD + c] = m;
}

// ================= attention path (gated on alpha != 0) ==================
__global__ void squeeze_kernel(const float* __restrict__ alpha) {
    if (alpha[0] == 0.0f) return;
    int c = threadIdx.x, b = blockIdx.x;
    float m = -3.4e38f;
    for (int p = 0; p < NP; p++)
        m = fmaxf(m, g_xh[((size_t)b * NP + p) * CD + c]);
    g_s[b * CD + c] = m;
}

__global__ void excite_kernel(const float* __restrict__ We1, const float* __restrict__ We2,
                              const float* __restrict__ alpha) {
    if (alpha[0] == 0.0f) return;
    int b = blockIdx.x, t = threadIdx.x;
    __shared__ float h[32];
    if (t < 32) {
        float a = 0.0f;
        for (int i = 0; i < CD; i++) a += We1[t * CD + i] * g_s[b * CD + i];
        h[t] = fmaxf(a, 0.0f);
    }
    __syncthreads();
    float a = 0.0f;
    for (int j = 0; j < 32; j++) a += We2[t * 32 + j] * h[j];
    g_e[b * CD + t] = 1.0f / (1.0f + expf(-a));
}

__global__ void qk_kernel(const float* __restrict__ Wq, const float* __restrict__ gq,
                          const float* __restrict__ bq, const float* __restrict__ Wk,
                          const float* __restrict__ gk, const float* __restrict__ bk,
                          const float* __restrict__ alpha) {
    if (alpha[0] == 0.0f) return;
    int c = threadIdx.x, o = blockIdx.x, b = blockIdx.y, which = blockIdx.z;
    const float* W  = which ? Wk : Wq;
    const float* g  = which ? gk : gq;
    const float* bt = which ? bk : bq;
    float acc = 0.0f;
    const float* xb = g_xh + (size_t)b * NP * CD + c;
    const float* wr = W + (size_t)o * NP;
    for (int p = 0; p < NP; p++) acc += wr[p] * xb[(size_t)p * CD];
    float s = g[o] / sqrtf(1.0f + 1e-5f);
    float v = fmaxf(acc * s + bt[o], 0.0f);
    float* dst = which ? g_kt : g_qt;
    dst[((size_t)b * CD + o) * CD + c] = v;
}

__global__ void sim_softmax_kernel(const float* __restrict__ alpha) {
    if (alpha[0] == 0.0f) return;
    int c = blockIdx.x, b = blockIdx.y, d = threadIdx.x;
    __shared__ float sb[32];
    int lane = d & 31, wid = d >> 5;
    const float* kb = g_kt + (size_t)b * CD * CD;
    const float* qb = g_qt + (size_t)b * CD * CD;
    float sim = 0.0f;
    for (int q = 0; q < CD; q++) sim += kb[q * CD + c] * qb[q * CD + d];
    // softmax(rowmax - sim) == exp(rowmin - sim)/sum(exp(rowmin - sim))
    float mn = sim;
#pragma unroll
    for (int o = 16; o; o >>= 1) mn = fminf(mn, __shfl_xor_sync(0xffffffffu, mn, o));
    if (lane == 0) sb[wid] = mn;
    __syncthreads();
    float Mn = sb[0];
    for (int w = 1; w < 8; w++) Mn = fminf(Mn, sb[w]);
    __syncthreads();
    float num = expf(Mn - sim);
    float sm = num;
#pragma unroll
    for (int o = 16; o; o >>= 1) sm += __shfl_xor_sync(0xffffffffu, sm, o);
    if (lane == 0) sb[wid] = sm;
    __syncthreads();
    float S = 0.0f;
    for (int w = 0; w < 8; w++) S += sb[w];
    g_aff[((size_t)b * CD + c) * CD + d] = num / S;
}

// ================= final write: out[b,c,p] = alpha*(aff@v)[c,p] + x[c,p] ========
__global__ void final_write_kernel(float* __restrict__ out, const float* __restrict__ alpha) {
    int p = blockIdx.x * blockDim.x + threadIdx.x;
    int c = blockIdx.y, b = blockIdx.z;
    float a = alpha[0];
    float base = g_xh[((size_t)b * NP + p) * CD + c];
    float res = base;
    if (a != 0.0f) {
        const float* affr = g_aff + ((size_t)b * CD + c) * CD;
        const float* xhp  = g_xh + ((size_t)b * NP + p) * CD;
        const float* eb   = g_e + b * CD;
        float acc = 0.0f;
        for (int d = 0; d < CD; d++) acc += affr[d] * xhp[d] * eb[d];
        res = a * acc + base;
    }
    out[NB * NP * 3 + ((size_t)b * CD + c) * NP + p] = res;
}

// ================= host launcher ==================
extern "C" void kernel_launch(void* const* d_in, const int* in_sizes, int n_in,
                              void* d_out, int out_size) {
    const float* xyz  = (const float*)d_in[0];
    const float* feat = (const float*)d_in[1];
    const float* W1 = (const float*)d_in[2];
    const float* g1 = (const float*)d_in[3];
    const float* b1 = (const float*)d_in[4];
    const float* W2 = (const float*)d_in[5];
    const float* g2 = (const float*)d_in[6];
    const float* b2 = (const float*)d_in[7];
    const float* W3 = (const float*)d_in[8];
    const float* g3 = (const float*)d_in[9];
    const float* b3 = (const float*)d_in[10];
    const float* Wq = (const float*)d_in[11];
    const float* gq = (const float*)d_in[12];
    const float* bq = (const float*)d_in[13];
    const float* Wk = (const float*)d_in[14];
    const float* gk = (const float*)d_in[15];
    const float* bk = (const float*)d_in[16];
    const float* We1 = (const float*)d_in[17];
    const float* We2 = (const float*)d_in[18];
    const float* alpha = (const float*)d_in[19];
    float* out = (float*)d_out;

    cudaFuncSetAttribute(fps_cluster_kernel,
                         cudaFuncAttributeMaxDynamicSharedMemorySize, FPS_SMEM);

    fps_cluster_kernel<<<NB * CLS, FT, FPS_SMEM>>>(xyz);
    gather_new_kernel<<<(NB * NP * 3 + 255) / 256, 256>>>(xyz, out);
    ball_query_kernel<<<(NB * NP) / 8, 256>>>(xyz);
    transpose_feat_kernel<<<dim3(NN / 32, CIN / 32, NB), dim3(32, 8)>>>(feat);
    pad_w1_kernel<<<64, KP1>>>(W1);
    build_g_kernel<<<NROWS, KP1>>>(xyz);
    gemm_bn_relu<1><<<dim3(NROWS / 64, 1), 256>>>(W1, g1, b1);
    gemm_bn_relu<2><<<dim3(NROWS / 64, 2), 256>>>(W2, g2, b2);
    gemm_bn_relu<3><<<dim3(NROWS / 64, 4), 256>>>(W3, g3, b3);
    maxpool_kernel<<<NB * NP, CD>>>();
    // attention path (device-gated on alpha[0] != 0; alpha==0 in this dataset)
    squeeze_kernel<<<NB, CD>>>(alpha);
    excite_kernel<<<NB, CD>>>(We1, We2, alpha);
    qk_kernel<<<dim3(CD, NB, 2), CD>>>(Wq, gq, bq, Wk, gk, bk, alpha);
    sim_softmax_kernel<<<dim3(CD, NB), CD>>>(alpha);
    final_write_kernel<<<dim3(NP / 256, CD, NB), 256>>>(out, alpha);
}

// round 13
// speedup vs baseline: 1.7808x; 1.2645x over previous
#include <cuda_runtime.h>
#include <cuda_bf16.h>
#include <cooperative_groups.h>
#include <math.h>
#include <stdint.h>

namespace cg = cooperative_groups;

// ---------------- problem constants ----------------
#define NB 2
#define NN 16384
#define CIN 64
#define NP 2048
#define NS 32
#define CD 256
#define KP1 80                  // 3+64=67 padded to 80
#define NROWS (NB*NP*NS)        // 131072

// FPS cluster config
#define FT 512                  // threads per FPS CTA
#define CLS 8                   // cluster size (CTAs per batch)
#define SHARD (NN / CLS)        // 2048 points owned per CTA
#define SLOTS (SHARD / FT)      // 4 slots per thread
#define FPS_SMEM (NN * 12)      // full copy: float2 xy + float z = 196608 B

// ---------------- scratch (device globals; no allocation allowed) ----------------
__device__ alignas(256) int   g_samp[NB * NP];
__device__ alignas(256) float g_newxyz[NB * NP * 3];
__device__ alignas(256) int   g_nn[NROWS];
__device__ alignas(256) float g_featT[(size_t)NB * NN * CIN];
__device__ alignas(256) float g_Wp1[64 * KP1];
__device__ alignas(256) float g_G[(size_t)NROWS * KP1];
__device__ alignas(256) float g_H1[(size_t)NROWS * 64];
__device__ alignas(256) float g_H2[(size_t)NROWS * 128];
__device__ alignas(256) float g_H3[(size_t)NROWS * 256];
__device__ alignas(256) float g_xh[(size_t)NB * NP * CD];   // (b,p,c)
__device__ alignas(256) float g_qt[(size_t)NB * CD * CD];
__device__ alignas(256) float g_kt[(size_t)NB * CD * CD];
__device__ alignas(256) float g_aff[(size_t)NB * CD * CD];
__device__ alignas(256) float g_s[NB * CD];
__device__ alignas(256) float g_e[NB * CD];

// ---------------- small PTX helpers ----------------
__device__ __forceinline__ uint32_t smem_u32(const void* p) {
    uint32_t a;
    asm("{ .reg .u64 t; cvta.to.shared.u64 t, %1; cvt.u32.u64 %0, t; }" : "=r"(a) : "l"(p));
    return a;
}
__device__ __forceinline__ uint32_t mapa_u32(uint32_t laddr, uint32_t rank) {
    uint32_t r;
    asm("mapa.shared::cluster.u32 %0, %1, %2;" : "=r"(r) : "r"(laddr), "r"(rank));
    return r;
}
__device__ __forceinline__ void mbar_init(uint32_t mbar, uint32_t cnt) {
    asm volatile("mbarrier.init.shared.b64 [%0], %1;" :: "r"(mbar), "r"(cnt) : "memory");
}
__device__ __forceinline__ void mbar_expect_tx(uint32_t mbar, uint32_t bytes) {
    asm volatile("mbarrier.arrive.expect_tx.shared.b64 _, [%0], %1;"
                 :: "r"(mbar), "r"(bytes) : "memory");
}
__device__ __forceinline__ void st_async_cluster_u64(uint32_t raddr, unsigned long long v,
                                                     uint32_t rmbar) {
    asm volatile("st.async.shared::cluster.mbarrier::complete_tx::bytes.b64 [%0], %1, [%2];"
                 :: "r"(raddr), "l"(v), "r"(rmbar) : "memory");
}
__device__ __forceinline__ void mbar_wait_parity(uint32_t mbar, uint32_t parity) {
    uint32_t done;
    asm volatile(
        "{\n\t.reg .pred p;\n\t"
        "mbarrier.try_wait.parity.acquire.cta.shared::cta.b64 p, [%1], %2;\n\t"
        "selp.b32 %0, 1, 0, p;\n\t}"
        : "=r"(done) : "r"(mbar), "r"(parity) : "memory");
    if (!done) {
        asm volatile(
            "{\n\t.reg .pred P1;\n\t"
            "WL_%=:\n\t"
            "mbarrier.try_wait.parity.acquire.cta.shared::cta.b64 P1, [%0], %1, 0x989680;\n\t"
            "@P1 bra.uni WD_%=;\n\t"
            "bra.uni WL_%=;\n\t"
            "WD_%=:\n\t}"
            :: "r"(mbar), "r"(parity) : "memory");
    }
}

// ================= FPS (cluster-distributed, push-based mbarrier exchange) =========
// 8 CTAs per batch. Full smem copy of points per CTA; min-dist updated only for
// own 2048-point shard. Per iteration each CTA reduces its shard to one packed
// key (dist_bits<<32 | ~index; max == max dist, ties -> smallest index, exact
// jnp.argmax). Exchange: warp0 lanes 0..7 push the key into all 8 CTAs' cand
// slot via st.async (+complete_tx on the receiver's mbarrier); receiver's
// leader contributes arrive.expect_tx(64B). Two mbarriers / two buffers
// (parity-indexed) keep phases and WAR reuse safe without any cluster.sync.
extern __shared__ unsigned char fps_sm[];

__global__ void __cluster_dims__(CLS, 1, 1) __launch_bounds__(FT, 1)
fps_cluster_kernel(const float* __restrict__ xyz) {
    float2* xy = (float2*)fps_sm;
    float*  zz = (float*)(fps_sm + (size_t)NN * sizeof(float2));
    __shared__ unsigned long long swarp[FT / 32];
    __shared__ alignas(16) unsigned long long cand[2][CLS];
    __shared__ alignas(8)  unsigned long long mbar[2];

    cg::cluster_group cluster = cg::this_cluster();
    const unsigned rank = cluster.block_rank();
    const int b = blockIdx.x / CLS;
    const int t = threadIdx.x;
    const int lane = t & 31, wid = t >> 5;
    const int base = rank * SHARD;

    // full local copy of this batch's points
    const float* xb = xyz + (size_t)b * NN * 3;
    for (int p = t; p < NN; p += FT) {
        xy[p] = make_float2(xb[p * 3 + 0], xb[p * 3 + 1]);
        zz[p] = xb[p * 3 + 2];
    }
    float mind[SLOTS];
#pragma unroll
    for (int s = 0; s < SLOTS; s++) mind[s] = 3.4e38f;

    uint32_t mb0 = smem_u32(&mbar[0]);
    uint32_t mb1 = smem_u32(&mbar[1]);
    if (t == 0) {
        mbar_init(mb0, 1);
        mbar_init(mb1, 1);
        if (rank == 0) g_samp[b * NP + 0] = 0;
    }
    // publish smem copy + mbarrier init to the cluster (one-time)
    cluster.sync();

    // remote addresses for warp0 lanes 0..7 (peer = lane)
    uint32_t rc0 = 0, rc1 = 0, rm0 = 0, rm1 = 0;
    if (wid == 0 && lane < CLS) {
        uint32_t lc0 = smem_u32(&cand[0][rank]);
        uint32_t lc1 = smem_u32(&cand[1][rank]);
        rc0 = mapa_u32(lc0, lane);
        rc1 = mapa_u32(lc1, lane);
        rm0 = mapa_u32(mb0, lane);
        rm1 = mapa_u32(mb1, lane);
    }

    int cur = 0;
    for (int i = 1; i < NP; i++) {
        float2 cxy = xy[cur];
        float  cz  = zz[cur];
        unsigned long long best = 0ull;
#pragma unroll
        for (int s = 0; s < SLOTS; s++) {
            int p = base + t + s * FT;
            float2 a = xy[p];
            float dx = a.x - cxy.x, dy = a.y - cxy.y, dz = zz[p] - cz;
            float d = dx * dx + dy * dy + dz * dz;     // identical expr to R11/R12
            float m = fminf(mind[s], d);
            mind[s] = m;
            unsigned long long key =
                ((unsigned long long)__float_as_uint(m) << 32) | (unsigned)(~p);
            best = (key > best) ? key : best;
        }
#pragma unroll
        for (int o = 16; o; o >>= 1) {
            unsigned long long v = __shfl_xor_sync(0xffffffffu, best, o);
            best = (v > best) ? v : best;
        }
        if (lane == 0) swarp[wid] = best;
        __syncthreads();

        const int bi = (i - 1) & 1;                  // buffer / mbarrier index
        const uint32_t ph = ((unsigned)(i - 1) >> 1) & 1u;  // phase parity of mbar[bi]
        if (wid == 0) {
            unsigned long long v = (lane < FT / 32) ? swarp[lane] : 0ull;
#pragma unroll
            for (int o = 16; o; o >>= 1) {
                unsigned long long v2 = __shfl_xor_sync(0xffffffffu, v, o);
                v = (v2 > v) ? v2 : v;
            }
            if (lane == 0) mbar_expect_tx(bi ? mb1 : mb0, CLS * 8u);
            if (lane < CLS)
                st_async_cluster_u64(bi ? rc1 : rc0, v, bi ? rm1 : rm0);
        }
        // all threads wait for all 8 candidates to land locally
        mbar_wait_parity(bi ? mb1 : mb0, ph);
        unsigned long long w = cand[bi][0];
#pragma unroll
        for (int j = 1; j < CLS; j++) {
            unsigned long long v2 = cand[bi][j];
            w = (v2 > w) ? v2 : w;
        }
        cur = (int)(~(unsigned)w);
        if (rank == 0 && t == 0) g_samp[b * NP + i] = cur;
    }
}

// ================= gather new_xyz (also writes first section of d_out) ============
__global__ void gather_new_kernel(const float* __restrict__ xyz, float* __restrict__ out) {
    int i = blockIdx.x * blockDim.x + threadIdx.x;
    if (i >= NB * NP * 3) return;
    int bp = i / 3, k = i - bp * 3;
    int b = bp / NP;
    int idx = g_samp[bp];
    float v = xyz[((size_t)b * NN + idx) * 3 + k];
    out[i] = v;
    g_newxyz[i] = v;
}

// ================= ball query: first NS in-range by ascending index, pad w/ first hit
__global__ void ball_query_kernel(const float* __restrict__ xyz) {
    int gw = (blockIdx.x * blockDim.x + threadIdx.x) >> 5;
    int lane = threadIdx.x & 31;
    if (gw >= NB * NP) return;
    int b = gw / NP;
    float cx = g_newxyz[gw * 3 + 0], cy = g_newxyz[gw * 3 + 1], cz = g_newxyz[gw * 3 + 2];
    const float* xb = xyz + (size_t)b * NN * 3;
    int base = gw * NS;
    int cnt = 0, first = -1;
    const float rr = 0.8f * 0.8f;
    for (int c0 = 0; c0 < NN; c0 += 32) {
        int j = c0 + lane;
        float dx = cx - xb[j * 3 + 0];
        float dy = cy - xb[j * 3 + 1];
        float dz = cz - xb[j * 3 + 2];
        float d = dx * dx + dy * dy + dz * dz;
        bool in = d < rr;
        unsigned m = __ballot_sync(0xffffffffu, in);
        if (first < 0 && m) first = c0 + (__ffs(m) - 1);
        if (in) {
            int pos = cnt + __popc(m & ((1u << lane) - 1u));
            if (pos < NS) g_nn[base + pos] = j;
        }
        cnt += __popc(m);
        if (cnt >= NS) break;
    }
    if (cnt < NS) {
        for (int k = cnt + lane; k < NS; k += 32) g_nn[base + k] = first;
    }
}

// ================= transpose features (B,C,N) -> (B,N,C) ==================
__global__ void transpose_feat_kernel(const float* __restrict__ f) {
    __shared__ float tile[32][33];
    int b = blockIdx.z;
    int n0 = blockIdx.x * 32, c0 = blockIdx.y * 32;
#pragma unroll
    for (int r = 0; r < 4; r++) {
        int c = c0 + threadIdx.y + r * 8;
        tile[threadIdx.y + r * 8][threadIdx.x] =
            f[((size_t)b * CIN + c) * NN + n0 + threadIdx.x];
    }
    __syncthreads();
#pragma unroll
    for (int r = 0; r < 4; r++) {
        int n = n0 + threadIdx.y + r * 8;
        g_featT[((size_t)b * NN + n) * CIN + c0 + threadIdx.x] =
            tile[threadIdx.x][threadIdx.y + r * 8];
    }
}

// ================= pad W1 (64x67) -> (64x80) ==================
__global__ void pad_w1_kernel(const float* __restrict__ W1) {
    int o = blockIdx.x, k = threadIdx.x;
    g_Wp1[o * KP1 + k] = (k < 67) ? W1[o * 67 + k] : 0.0f;
}

// ================= build grouped matrix G (NROWS x 80) ==================
__global__ void build_g_kernel(const float* __restrict__ xyz) {
    int row = blockIdx.x;
    int k = threadIdx.x;            // 0..79
    int b = row / (NP * NS);
    int rem = row - b * (NP * NS);
    int p = rem / NS;
    int nn = g_nn[row];
    float v = 0.0f;
    if (k < 3)       v = xyz[((size_t)b * NN + nn) * 3 + k] - g_newxyz[(b * NP + p) * 3 + k];
    else if (k < 67) v = g_featT[((size_t)b * NN + nn) * CIN + (k - 3)];
    g_G[(size_t)row * KP1 + k] = v;
}

// ================= GEMM + BN(eval) + ReLU ==================
// C[m,n] = relu( (sum_k A[m,k]*W[n,k]) * g[n]/sqrt(1+eps) + b[n] )
template<int LAYER>
__global__ void __launch_bounds__(256) gemm_bn_relu(const float* __restrict__ W,
                                                    const float* __restrict__ gs,
                                                    const float* __restrict__ bt) {
    constexpr int K = (LAYER == 1) ? KP1 : ((LAYER == 2) ? 64 : 128);
    constexpr int N = (LAYER == 1) ? 64 : ((LAYER == 2) ? 128 : 256);
    const float* A = (LAYER == 1) ? (const float*)g_G
                   : (LAYER == 2) ? (const float*)g_H1 : (const float*)g_H2;
    float* C = (LAYER == 1) ? (float*)g_H1
             : (LAYER == 2) ? (float*)g_H2 : (float*)g_H3;
    const float* Wp = (LAYER == 1) ? (const float*)g_Wp1 : W;

    __shared__ float As[16][65];
    __shared__ float Ws[16][65];
    int tid = threadIdx.x;
    int tx = tid & 15, ty = tid >> 4;
    int m0 = blockIdx.x * 64, n0 = blockIdx.y * 64;
    int lm = tid >> 2, lk = (tid & 3) * 4;
    const float* Ag = A  + (size_t)(m0 + lm) * K + lk;
    const float* Wg = Wp + (size_t)(n0 + lm) * K + lk;
    float acc[4][4] = {};

    for (int kt = 0; kt < K; kt += 16) {
        float4 av = *(const float4*)(Ag + kt);
        float4 wv = *(const float4*)(Wg + kt);
        As[lk + 0][lm] = av.x; As[lk + 1][lm] = av.y; As[lk + 2][lm] = av.z; As[lk + 3][lm] = av.w;
        Ws[lk + 0][lm] = wv.x; Ws[lk + 1][lm] = wv.y; Ws[lk + 2][lm] = wv.z; Ws[lk + 3][lm] = wv.w;
        __syncthreads();
#pragma unroll
        for (int k = 0; k < 16; k++) {
            float a[4], bb[4];
#pragma unroll
            for (int i2 = 0; i2 < 4; i2++) a[i2] = As[k][ty * 4 + i2];
#pragma unroll
            for (int j = 0; j < 4; j++) bb[j] = Ws[k][tx * 4 + j];
#pragma unroll
            for (int i2 = 0; i2 < 4; i2++)
#pragma unroll
                for (int j = 0; j < 4; j++) acc[i2][j] = fmaf(a[i2], bb[j], acc[i2][j]);
        }
        __syncthreads();
    }
#pragma unroll
    for (int j = 0; j < 4; j++) {
        int n = n0 + tx * 4 + j;
        float s = gs[n] / sqrtf(1.0f + 1e-5f);
        float bb = bt[n];
#pragma unroll
        for (int i2 = 0; i2 < 4; i2++) {
            int m = m0 + ty * 4 + i2;
            C[(size_t)m * N + n] = fmaxf(fmaf(acc[i2][j], s, bb), 0.0f);
        }
    }
}

// ================= maxpool over NS samples -> xh (b,p,c) ==================
__global__ void maxpool_kernel() {
    int c = threadIdx.x;            // 256
    int bp = blockIdx.x;            // NB*NP
    const float* base = g_H3 + (size_t)bp * NS * CD + c;
    float m = base[0];
#pragma unroll
    for (int s = 1; s < NS; s++) m = fmaxf(m, base[(size_t)s * CD]);
    g_xh[(size_t)bp * CD + c] = m;
}

// ================= attention path (gated on alpha != 0) ==================
__global__ void squeeze_kernel(const float* __restrict__ alpha) {
    if (alpha[0] == 0.0f) return;
    int c = threadIdx.x, b = blockIdx.x;
    float m = -3.4e38f;
    for (int p = 0; p < NP; p++)
        m = fmaxf(m, g_xh[((size_t)b * NP + p) * CD + c]);
    g_s[b * CD + c] = m;
}

__global__ void excite_kernel(const float* __restrict__ We1, const float* __restrict__ We2,
                              const float* __restrict__ alpha) {
    if (alpha[0] == 0.0f) return;
    int b = blockIdx.x, t = threadIdx.x;
    __shared__ float h[32];
    if (t < 32) {
        float a = 0.0f;
        for (int i = 0; i < CD; i++) a += We1[t * CD + i] * g_s[b * CD + i];
        h[t] = fmaxf(a, 0.0f);
    }
    __syncthreads();
    float a = 0.0f;
    for (int j = 0; j < 32; j++) a += We2[t * 32 + j] * h[j];
    g_e[b * CD + t] = 1.0f / (1.0f + expf(-a));
}

__global__ void qk_kernel(const float* __restrict__ Wq, const float* __restrict__ gq,
                          const float* __restrict__ bq, const float* __restrict__ Wk,
                          const float* __restrict__ gk, const float* __restrict__ bk,
                          const float* __restrict__ alpha) {
    if (alpha[0] == 0.0f) return;
    int c = threadIdx.x, o = blockIdx.x, b = blockIdx.y, which = blockIdx.z;
    const float* W  = which ? Wk : Wq;
    const float* g  = which ? gk : gq;
    const float* bt = which ? bk : bq;
    float acc = 0.0f;
    const float* xb = g_xh + (size_t)b * NP * CD + c;
    const float* wr = W + (size_t)o * NP;
    for (int p = 0; p < NP; p++) acc += wr[p] * xb[(size_t)p * CD];
    float s = g[o] / sqrtf(1.0f + 1e-5f);
    float v = fmaxf(acc * s + bt[o], 0.0f);
    float* dst = which ? g_kt : g_qt;
    dst[((size_t)b * CD + o) * CD + c] = v;
}

__global__ void sim_softmax_kernel(const float* __restrict__ alpha) {
    if (alpha[0] == 0.0f) return;
    int c = blockIdx.x, b = blockIdx.y, d = threadIdx.x;
    __shared__ float sb[32];
    int lane = d & 31, wid = d >> 5;
    const float* kb = g_kt + (size_t)b * CD * CD;
    const float* qb = g_qt + (size_t)b * CD * CD;
    float sim = 0.0f;
    for (int q = 0; q < CD; q++) sim += kb[q * CD + c] * qb[q * CD + d];
    // softmax(rowmax - sim) == exp(rowmin - sim)/sum(exp(rowmin - sim))
    float mn = sim;
#pragma unroll
    for (int o = 16; o; o >>= 1) mn = fminf(mn, __shfl_xor_sync(0xffffffffu, mn, o));
    if (lane == 0) sb[wid] = mn;
    __syncthreads();
    float Mn = sb[0];
    for (int w = 1; w < 8; w++) Mn = fminf(Mn, sb[w]);
    __syncthreads();
    float num = expf(Mn - sim);
    float sm = num;
#pragma unroll
    for (int o = 16; o; o >>= 1) sm += __shfl_xor_sync(0xffffffffu, sm, o);
    if (lane == 0) sb[wid] = sm;
    __syncthreads();
    float S = 0.0f;
    for (int w = 0; w < 8; w++) S += sb[w];
    g_aff[((size_t)b * CD + c) * CD + d] = num / S;
}

// ================= final write: out[b,c,p] = alpha*(aff@v)[c,p] + x[c,p] ========
__global__ void final_write_kernel(float* __restrict__ out, const float* __restrict__ alpha) {
    int p = blockIdx.x * blockDim.x + threadIdx.x;
    int c = blockIdx.y, b = blockIdx.z;
    float a = alpha[0];
    float base = g_xh[((size_t)b * NP + p) * CD + c];
    float res = base;
    if (a != 0.0f) {
        const float* affr = g_aff + ((size_t)b * CD + c) * CD;
        const float* xhp  = g_xh + ((size_t)b * NP + p) * CD;
        const float* eb   = g_e + b * CD;
        float acc = 0.0f;
        for (int d = 0; d < CD; d++) acc += affr[d] * xhp[d] * eb[d];
        res = a * acc + base;
    }
    out[NB * NP * 3 + ((size_t)b * CD + c) * NP + p] = res;
}

// ================= host launcher ==================
extern "C" void kernel_launch(void* const* d_in, const int* in_sizes, int n_in,
                              void* d_out, int out_size) {
    const float* xyz  = (const float*)d_in[0];
    const float* feat = (const float*)d_in[1];
    const float* W1 = (const float*)d_in[2];
    const float* g1 = (const float*)d_in[3];
    const float* b1 = (const float*)d_in[4];
    const float* W2 = (const float*)d_in[5];
    const float* g2 = (const float*)d_in[6];
    const float* b2 = (const float*)d_in[7];
    const float* W3 = (const float*)d_in[8];
    const float* g3 = (const float*)d_in[9];
    const float* b3 = (const float*)d_in[10];
    const float* Wq = (const float*)d_in[11];
    const float* gq = (const float*)d_in[12];
    const float* bq = (const float*)d_in[13];
    const float* Wk = (const float*)d_in[14];
    const float* gk = (const float*)d_in[15];
    const float* bk = (const float*)d_in[16];
    const float* We1 = (const float*)d_in[17];
    const float* We2 = (const float*)d_in[18];
    const float* alpha = (const float*)d_in[19];
    float* out = (float*)d_out;

    cudaFuncSetAttribute(fps_cluster_kernel,
                         cudaFuncAttributeMaxDynamicSharedMemorySize, FPS_SMEM);

    fps_cluster_kernel<<<NB * CLS, FT, FPS_SMEM>>>(xyz);
    gather_new_kernel<<<(NB * NP * 3 + 255) / 256, 256>>>(xyz, out);
    ball_query_kernel<<<(NB * NP) / 8, 256>>>(xyz);
    transpose_feat_kernel<<<dim3(NN / 32, CIN / 32, NB), dim3(32, 8)>>>(feat);
    pad_w1_kernel<<<64, KP1>>>(W1);
    build_g_kernel<<<NROWS, KP1>>>(xyz);
    gemm_bn_relu<1><<<dim3(NROWS / 64, 1), 256>>>(W1, g1, b1);
    gemm_bn_relu<2><<<dim3(NROWS / 64, 2), 256>>>(W2, g2, b2);
    gemm_bn_relu<3><<<dim3(NROWS / 64, 4), 256>>>(W3, g3, b3);
    maxpool_kernel<<<NB * NP, CD>>>();
    // attention path (device-gated on alpha[0] != 0; alpha==0 in this dataset)
    squeeze_kernel<<<NB, CD>>>(alpha);
    excite_kernel<<<NB, CD>>>(We1, We2, alpha);
    qk_kernel<<<dim3(CD, NB, 2), CD>>>(Wq, gq, bq, Wk, gk, bk, alpha);
    sim_softmax_kernel<<<dim3(CD, NB), CD>>>(alpha);
    final_write_kernel<<<dim3(NP / 256, CD, NB), 256>>>(out, alpha);
}

// round 14
// speedup vs baseline: 2.4011x; 1.3483x over previous
#include <cuda_runtime.h>
#include <cuda_bf16.h>
#include <cooperative_groups.h>
#include <math.h>
#include <stdint.h>

namespace cg = cooperative_groups;

// ---------------- problem constants ----------------
#define NB 2
#define NN 16384
#define CIN 64
#define NP 2048
#define NS 32
#define CD 256
#define KP1 80                  // 3+64=67 padded to 80
#define NROWS (NB*NP*NS)        // 131072

// FPS cluster config
#define FT 256                  // threads per FPS CTA
#define CLS 8                   // cluster size (CTAs per batch)
#define SHARD (NN / CLS)        // 2048 points owned per CTA
#define SLOTS (SHARD / FT)      // 8 slots per thread (register-resident coords)
#define FPS_SMEM (NN * 12)      // full copy: float2 xy + float z = 196608 B

// ---------------- scratch (device globals; no allocation allowed) ----------------
__device__ alignas(256) int   g_samp[NB * NP];
__device__ alignas(256) float g_newxyz[NB * NP * 3];
__device__ alignas(256) int   g_nn[NROWS];
__device__ alignas(256) float g_featT[(size_t)NB * NN * CIN];
__device__ alignas(256) float g_Wp1[64 * KP1];
__device__ alignas(256) float g_G[(size_t)NROWS * KP1];
__device__ alignas(256) float g_H1[(size_t)NROWS * 64];
__device__ alignas(256) float g_H2[(size_t)NROWS * 128];
__device__ alignas(256) float g_H3[(size_t)NROWS * 256];
__device__ alignas(256) float g_xh[(size_t)NB * NP * CD];   // (b,p,c)
__device__ alignas(256) float g_qt[(size_t)NB * CD * CD];
__device__ alignas(256) float g_kt[(size_t)NB * CD * CD];
__device__ alignas(256) float g_aff[(size_t)NB * CD * CD];
__device__ alignas(256) float g_s[NB * CD];
__device__ alignas(256) float g_e[NB * CD];

// ---------------- small PTX helpers ----------------
__device__ __forceinline__ uint32_t smem_u32(const void* p) {
    uint32_t a;
    asm("{ .reg .u64 t; cvta.to.shared.u64 t, %1; cvt.u32.u64 %0, t; }" : "=r"(a) : "l"(p));
    return a;
}
__device__ __forceinline__ uint32_t mapa_u32(uint32_t laddr, uint32_t rank) {
    uint32_t r;
    asm("mapa.shared::cluster.u32 %0, %1, %2;" : "=r"(r) : "r"(laddr), "r"(rank));
    return r;
}
__device__ __forceinline__ void mbar_init(uint32_t mbar, uint32_t cnt) {
    asm volatile("mbarrier.init.shared.b64 [%0], %1;" :: "r"(mbar), "r"(cnt) : "memory");
}
__device__ __forceinline__ void mbar_expect_tx(uint32_t mbar, uint32_t bytes) {
    asm volatile("mbarrier.arrive.expect_tx.shared.b64 _, [%0], %1;"
                 :: "r"(mbar), "r"(bytes) : "memory");
}
__device__ __forceinline__ void st_async_cluster_u64(uint32_t raddr, unsigned long long v,
                                                     uint32_t rmbar) {
    asm volatile("st.async.shared::cluster.mbarrier::complete_tx::bytes.b64 [%0], %1, [%2];"
                 :: "r"(raddr), "l"(v), "r"(rmbar) : "memory");
}
__device__ __forceinline__ void mbar_wait_parity(uint32_t mbar, uint32_t parity) {
    uint32_t done;
    asm volatile(
        "{\n\t.reg .pred p;\n\t"
        "mbarrier.try_wait.parity.acquire.cta.shared::cta.b64 p, [%1], %2;\n\t"
        "selp.b32 %0, 1, 0, p;\n\t}"
        : "=r"(done) : "r"(mbar), "r"(parity) : "memory");
    if (!done) {
        asm volatile(
            "{\n\t.reg .pred P1;\n\t"
            "WL_%=:\n\t"
            "mbarrier.try_wait.parity.acquire.cta.shared::cta.b64 P1, [%0], %1, 0x989680;\n\t"
            "@P1 bra.uni WD_%=;\n\t"
            "bra.uni WL_%=;\n\t"
            "WD_%=:\n\t}"
            :: "r"(mbar), "r"(parity) : "memory");
    }
}

// ================= FPS (cluster-distributed, push exchange, register coords) =======
// 8 CTAs per batch. Own-shard coordinates live in REGISTERS (8 pts/thread);
// the full SMEM copy exists only to fetch the winner's coordinates. Per
// iteration each CTA reduces its shard to one packed key
// (dist_bits<<32 | ~index; max == max dist, ties -> smallest index, exact
// jnp.argmax). Warp/block reduces use REDUX (max on dist bits, min on index
// among matching lanes). Exchange: warp0 lanes 0..7 push the key into all 8
// CTAs via st.async + complete_tx on the receiver's mbarrier; two
// mbarriers/buffers (parity-indexed) keep phases and WAR reuse safe.
extern __shared__ unsigned char fps_sm[];

__global__ void __cluster_dims__(CLS, 1, 1) __launch_bounds__(FT, 1)
fps_cluster_kernel(const float* __restrict__ xyz) {
    float2* xy = (float2*)fps_sm;
    float*  zz = (float*)(fps_sm + (size_t)NN * sizeof(float2));
    __shared__ unsigned long long swarp[FT / 32];
    __shared__ alignas(16) unsigned long long cand[2][CLS];
    __shared__ alignas(8)  unsigned long long mbar[2];

    cg::cluster_group cluster = cg::this_cluster();
    const unsigned rank = cluster.block_rank();
    const int b = blockIdx.x / CLS;
    const int t = threadIdx.x;
    const int lane = t & 31, wid = t >> 5;
    const int base = rank * SHARD;

    // full local copy of this batch's points (for winner-coordinate lookup)
    const float* xb = xyz + (size_t)b * NN * 3;
    for (int p = t; p < NN; p += FT) {
        xy[p] = make_float2(xb[p * 3 + 0], xb[p * 3 + 1]);
        zz[p] = xb[p * 3 + 2];
    }

    uint32_t mb0 = smem_u32(&mbar[0]);
    uint32_t mb1 = smem_u32(&mbar[1]);
    if (t == 0) {
        mbar_init(mb0, 1);
        mbar_init(mb1, 1);
        if (rank == 0) g_samp[b * NP + 0] = 0;
    }
    // publish smem copy + mbarrier init to the cluster (one-time)
    cluster.sync();

    // own-shard coordinates in registers
    float px[SLOTS], py[SLOTS], pz[SLOTS], mind[SLOTS];
#pragma unroll
    for (int s = 0; s < SLOTS; s++) {
        int p = base + t + s * FT;
        float2 a = xy[p];
        px[s] = a.x; py[s] = a.y; pz[s] = zz[p];
        mind[s] = 3.4e38f;
    }

    // remote addresses for warp0 lanes 0..7 (peer = lane)
    uint32_t rc0 = 0, rc1 = 0, rm0 = 0, rm1 = 0;
    if (wid == 0 && lane < CLS) {
        uint32_t lc0 = smem_u32(&cand[0][rank]);
        uint32_t lc1 = smem_u32(&cand[1][rank]);
        rc0 = mapa_u32(lc0, lane);
        rc1 = mapa_u32(lc1, lane);
        rm0 = mapa_u32(mb0, lane);
        rm1 = mapa_u32(mb1, lane);
    }

    int cur = 0;
    for (int i = 1; i < NP; i++) {
        float2 cxy = xy[cur];
        float  cz  = zz[cur];
        float bestm = -1.0f; unsigned bidx = 0;
#pragma unroll
        for (int s = 0; s < SLOTS; s++) {
            float dx = px[s] - cxy.x, dy = py[s] - cxy.y, dz = pz[s] - cz;
            float d = dx * dx + dy * dy + dz * dz;     // identical expr to R11-R13
            float m = fminf(mind[s], d);
            mind[s] = m;
            if (m > bestm) { bestm = m; bidx = (unsigned)(base + t + s * FT); }
        }
        // warp reduce: max dist bits, then min index among matching lanes
        unsigned mb = __float_as_uint(bestm);          // bestm >= 0 -> bit-ordered
        unsigned wmax = __reduce_max_sync(0xffffffffu, mb);
        unsigned cidx = (mb == wmax) ? bidx : 0xffffffffu;
        unsigned widx = __reduce_min_sync(0xffffffffu, cidx);
        if (lane == 0)
            swarp[wid] = ((unsigned long long)wmax << 32) | (unsigned)(~widx);
        __syncthreads();

        const int bi = (i - 1) & 1;                  // buffer / mbarrier index
        const uint32_t ph = ((unsigned)(i - 1) >> 1) & 1u;  // phase parity of mbar[bi]
        if (wid == 0) {
            unsigned hi = 0, lo = 0;
            if (lane < FT / 32) {
                unsigned long long k = swarp[lane];
                hi = (unsigned)(k >> 32); lo = (unsigned)k;
            }
            unsigned mhi = __reduce_max_sync(0xffffffffu, hi);
            unsigned clo = (hi == mhi) ? lo : 0u;    // lo = ~idx; max ~idx == min idx
            unsigned mlo = __reduce_max_sync(0xffffffffu, clo);
            unsigned long long key = ((unsigned long long)mhi << 32) | mlo;
            if (lane == 0) mbar_expect_tx(bi ? mb1 : mb0, CLS * 8u);
            if (lane < CLS)
                st_async_cluster_u64(bi ? rc1 : rc0, key, bi ? rm1 : rm0);
        }
        // all threads wait for all 8 candidates to land locally
        mbar_wait_parity(bi ? mb1 : mb0, ph);
        unsigned long long w = cand[bi][0];
#pragma unroll
        for (int j = 1; j < CLS; j++) {
            unsigned long long v2 = cand[bi][j];
            w = (v2 > w) ? v2 : w;
        }
        cur = (int)(~(unsigned)w);
        if (rank == 0 && t == 0) g_samp[b * NP + i] = cur;
    }
}

// ================= gather new_xyz (also writes first section of d_out) ============
__global__ void gather_new_kernel(const float* __restrict__ xyz, float* __restrict__ out) {
    int i = blockIdx.x * blockDim.x + threadIdx.x;
    if (i >= NB * NP * 3) return;
    int bp = i / 3, k = i - bp * 3;
    int b = bp / NP;
    int idx = g_samp[bp];
    float v = xyz[((size_t)b * NN + idx) * 3 + k];
    out[i] = v;
    g_newxyz[i] = v;
}

// ================= ball query: first NS in-range by ascending index, pad w/ first hit
__global__ void ball_query_kernel(const float* __restrict__ xyz) {
    int gw = (blockIdx.x * blockDim.x + threadIdx.x) >> 5;
    int lane = threadIdx.x & 31;
    if (gw >= NB * NP) return;
    int b = gw / NP;
    float cx = g_newxyz[gw * 3 + 0], cy = g_newxyz[gw * 3 + 1], cz = g_newxyz[gw * 3 + 2];
    const float* xb = xyz + (size_t)b * NN * 3;
    int base = gw * NS;
    int cnt = 0, first = -1;
    const float rr = 0.8f * 0.8f;
    for (int c0 = 0; c0 < NN; c0 += 32) {
        int j = c0 + lane;
        float dx = cx - xb[j * 3 + 0];
        float dy = cy - xb[j * 3 + 1];
        float dz = cz - xb[j * 3 + 2];
        float d = dx * dx + dy * dy + dz * dz;
        bool in = d < rr;
        unsigned m = __ballot_sync(0xffffffffu, in);
        if (first < 0 && m) first = c0 + (__ffs(m) - 1);
        if (in) {
            int pos = cnt + __popc(m & ((1u << lane) - 1u));
            if (pos < NS) g_nn[base + pos] = j;
        }
        cnt += __popc(m);
        if (cnt >= NS) break;
    }
    if (cnt < NS) {
        for (int k = cnt + lane; k < NS; k += 32) g_nn[base + k] = first;
    }
}

// ================= transpose features (B,C,N) -> (B,N,C) ==================
__global__ void transpose_feat_kernel(const float* __restrict__ f) {
    __shared__ float tile[32][33];
    int b = blockIdx.z;
    int n0 = blockIdx.x * 32, c0 = blockIdx.y * 32;
#pragma unroll
    for (int r = 0; r < 4; r++) {
        int c = c0 + threadIdx.y + r * 8;
        tile[threadIdx.y + r * 8][threadIdx.x] =
            f[((size_t)b * CIN + c) * NN + n0 + threadIdx.x];
    }
    __syncthreads();
#pragma unroll
    for (int r = 0; r < 4; r++) {
        int n = n0 + threadIdx.y + r * 8;
        g_featT[((size_t)b * NN + n) * CIN + c0 + threadIdx.x] =
            tile[threadIdx.x][threadIdx.y + r * 8];
    }
}

// ================= pad W1 (64x67) -> (64x80) ==================
__global__ void pad_w1_kernel(const float* __restrict__ W1) {
    int o = blockIdx.x, k = threadIdx.x;
    g_Wp1[o * KP1 + k] = (k < 67) ? W1[o * 67 + k] : 0.0f;
}

// ================= build grouped matrix G (NROWS x 80) ==================
__global__ void build_g_kernel(const float* __restrict__ xyz) {
    int row = blockIdx.x;
    int k = threadIdx.x;            // 0..79
    int b = row / (NP * NS);
    int rem = row - b * (NP * NS);
    int p = rem / NS;
    int nn = g_nn[row];
    float v = 0.0f;
    if (k < 3)       v = xyz[((size_t)b * NN + nn) * 3 + k] - g_newxyz[(b * NP + p) * 3 + k];
    else if (k < 67) v = g_featT[((size_t)b * NN + nn) * CIN + (k - 3)];
    g_G[(size_t)row * KP1 + k] = v;
}

// ================= GEMM + BN(eval) + ReLU ==================
// C[m,n] = relu( (sum_k A[m,k]*W[n,k]) * g[n]/sqrt(1+eps) + b[n] )
template<int LAYER>
__global__ void __launch_bounds__(256) gemm_bn_relu(const float* __restrict__ W,
                                                    const float* __restrict__ gs,
                                                    const float* __restrict__ bt) {
    constexpr int K = (LAYER == 1) ? KP1 : ((LAYER == 2) ? 64 : 128);
    constexpr int N = (LAYER == 1) ? 64 : ((LAYER == 2) ? 128 : 256);
    const float* A = (LAYER == 1) ? (const float*)g_G
                   : (LAYER == 2) ? (const float*)g_H1 : (const float*)g_H2;
    float* C = (LAYER == 1) ? (float*)g_H1
             : (LAYER == 2) ? (float*)g_H2 : (float*)g_H3;
    const float* Wp = (LAYER == 1) ? (const float*)g_Wp1 : W;

    __shared__ float As[16][65];
    __shared__ float Ws[16][65];
    int tid = threadIdx.x;
    int tx = tid & 15, ty = tid >> 4;
    int m0 = blockIdx.x * 64, n0 = blockIdx.y * 64;
    int lm = tid >> 2, lk = (tid & 3) * 4;
    const float* Ag = A  + (size_t)(m0 + lm) * K + lk;
    const float* Wg = Wp + (size_t)(n0 + lm) * K + lk;
    float acc[4][4] = {};

    for (int kt = 0; kt < K; kt += 16) {
        float4 av = *(const float4*)(Ag + kt);
        float4 wv = *(const float4*)(Wg + kt);
        As[lk + 0][lm] = av.x; As[lk + 1][lm] = av.y; As[lk + 2][lm] = av.z; As[lk + 3][lm] = av.w;
        Ws[lk + 0][lm] = wv.x; Ws[lk + 1][lm] = wv.y; Ws[lk + 2][lm] = wv.z; Ws[lk + 3][lm] = wv.w;
        __syncthreads();
#pragma unroll
        for (int k = 0; k < 16; k++) {
            float a[4], bb[4];
#pragma unroll
            for (int i2 = 0; i2 < 4; i2++) a[i2] = As[k][ty * 4 + i2];
#pragma unroll
            for (int j = 0; j < 4; j++) bb[j] = Ws[k][tx * 4 + j];
#pragma unroll
            for (int i2 = 0; i2 < 4; i2++)
#pragma unroll
                for (int j = 0; j < 4; j++) acc[i2][j] = fmaf(a[i2], bb[j], acc[i2][j]);
        }
        __syncthreads();
    }
#pragma unroll
    for (int j = 0; j < 4; j++) {
        int n = n0 + tx * 4 + j;
        float s = gs[n] / sqrtf(1.0f + 1e-5f);
        float bb = bt[n];
#pragma unroll
        for (int i2 = 0; i2 < 4; i2++) {
            int m = m0 + ty * 4 + i2;
            C[(size_t)m * N + n] = fmaxf(fmaf(acc[i2][j], s, bb), 0.0f);
        }
    }
}

// ================= maxpool over NS samples -> xh (b,p,c) ==================
__global__ void maxpool_kernel() {
    int c = threadIdx.x;            // 256
    int bp = blockIdx.x;            // NB*NP
    const float* base = g_H3 + (size_t)bp * NS * CD + c;
    float m = base[0];
#pragma unroll
    for (int s = 1; s < NS; s++) m = fmaxf(m, base[(size_t)s * CD]);
    g_xh[(size_t)bp * CD + c] = m;
}

// ================= attention path (gated on alpha != 0) ==================
__global__ void squeeze_kernel(const float* __restrict__ alpha) {
    if (alpha[0] == 0.0f) return;
    int c = threadIdx.x, b = blockIdx.x;
    float m = -3.4e38f;
    for (int p = 0; p < NP; p++)
        m = fmaxf(m, g_xh[((size_t)b * NP + p) * CD + c]);
    g_s[b * CD + c] = m;
}

__global__ void excite_kernel(const float* __restrict__ We1, const float* __restrict__ We2,
                              const float* __restrict__ alpha) {
    if (alpha[0] == 0.0f) return;
    int b = blockIdx.x, t = threadIdx.x;
    __shared__ float h[32];
    if (t < 32) {
        float a = 0.0f;
        for (int i = 0; i < CD; i++) a += We1[t * CD + i] * g_s[b * CD + i];
        h[t] = fmaxf(a, 0.0f);
    }
    __syncthreads();
    float a = 0.0f;
    for (int j = 0; j < 32; j++) a += We2[t * 32 + j] * h[j];
    g_e[b * CD + t] = 1.0f / (1.0f + expf(-a));
}

__global__ void qk_kernel(const float* __restrict__ Wq, const float* __restrict__ gq,
                          const float* __restrict__ bq, const float* __restrict__ Wk,
                          const float* __restrict__ gk, const float* __restrict__ bk,
                          const float* __restrict__ alpha) {
    if (alpha[0] == 0.0f) return;
    int c = threadIdx.x, o = blockIdx.x, b = blockIdx.y, which = blockIdx.z;
    const float* W  = which ? Wk : Wq;
    const float* g  = which ? gk : gq;
    const float* bt = which ? bk : bq;
    float acc = 0.0f;
    const float* xb = g_xh + (size_t)b * NP * CD + c;
    const float* wr = W + (size_t)o * NP;
    for (int p = 0; p < NP; p++) acc += wr[p] * xb[(size_t)p * CD];
    float s = g[o] / sqrtf(1.0f + 1e-5f);
    float v = fmaxf(acc * s + bt[o], 0.0f);
    float* dst = which ? g_kt : g_qt;
    dst[((size_t)b * CD + o) * CD + c] = v;
}

__global__ void sim_softmax_kernel(const float* __restrict__ alpha) {
    if (alpha[0] == 0.0f) return;
    int c = blockIdx.x, b = blockIdx.y, d = threadIdx.x;
    __shared__ float sb[32];
    int lane = d & 31, wid = d >> 5;
    const float* kb = g_kt + (size_t)b * CD * CD;
    const float* qb = g_qt + (size_t)b * CD * CD;
    float sim = 0.0f;
    for (int q = 0; q < CD; q++) sim += kb[q * CD + c] * qb[q * CD + d];
    // softmax(rowmax - sim) == exp(rowmin - sim)/sum(exp(rowmin - sim))
    float mn = sim;
#pragma unroll
    for (int o = 16; o; o >>= 1) mn = fminf(mn, __shfl_xor_sync(0xffffffffu, mn, o));
    if (lane == 0) sb[wid] = mn;
    __syncthreads();
    float Mn = sb[0];
    for (int w = 1; w < 8; w++) Mn = fminf(Mn, sb[w]);
    __syncthreads();
    float num = expf(Mn - sim);
    float sm = num;
#pragma unroll
    for (int o = 16; o; o >>= 1) sm += __shfl_xor_sync(0xffffffffu, sm, o);
    if (lane == 0) sb[wid] = sm;
    __syncthreads();
    float S = 0.0f;
    for (int w = 0; w < 8; w++) S += sb[w];
    g_aff[((size_t)b * CD + c) * CD + d] = num / S;
}

// ================= final write: out[b,c,p] = alpha*(aff@v)[c,p] + x[c,p] ========
__global__ void final_write_kernel(float* __restrict__ out, const float* __restrict__ alpha) {
    int p = blockIdx.x * blockDim.x + threadIdx.x;
    int c = blockIdx.y, b = blockIdx.z;
    float a = alpha[0];
    float base = g_xh[((size_t)b * NP + p) * CD + c];
    float res = base;
    if (a != 0.0f) {
        const float* affr = g_aff + ((size_t)b * CD + c) * CD;
        const float* xhp  = g_xh + ((size_t)b * NP + p) * CD;
        const float* eb   = g_e + b * CD;
        float acc = 0.0f;
        for (int d = 0; d < CD; d++) acc += affr[d] * xhp[d] * eb[d];
        res = a * acc + base;
    }
    out[NB * NP * 3 + ((size_t)b * CD + c) * NP + p] = res;
}

// ================= host launcher ==================
extern "C" void kernel_launch(void* const* d_in, const int* in_sizes, int n_in,
                              void* d_out, int out_size) {
    const float* xyz  = (const float*)d_in[0];
    const float* feat = (const float*)d_in[1];
    const float* W1 = (const float*)d_in[2];
    const float* g1 = (const float*)d_in[3];
    const float* b1 = (const float*)d_in[4];
    const float* W2 = (const float*)d_in[5];
    const float* g2 = (const float*)d_in[6];
    const float* b2 = (const float*)d_in[7];
    const float* W3 = (const float*)d_in[8];
    const float* g3 = (const float*)d_in[9];
    const float* b3 = (const float*)d_in[10];
    const float* Wq = (const float*)d_in[11];
    const float* gq = (const float*)d_in[12];
    const float* bq = (const float*)d_in[13];
    const float* Wk = (const float*)d_in[14];
    const float* gk = (const float*)d_in[15];
    const float* bk = (const float*)d_in[16];
    const float* We1 = (const float*)d_in[17];
    const float* We2 = (const float*)d_in[18];
    const float* alpha = (const float*)d_in[19];
    float* out = (float*)d_out;

    cudaFuncSetAttribute(fps_cluster_kernel,
                         cudaFuncAttributeMaxDynamicSharedMemorySize, FPS_SMEM);

    fps_cluster_kernel<<<NB * CLS, FT, FPS_SMEM>>>(xyz);
    gather_new_kernel<<<(NB * NP * 3 + 255) / 256, 256>>>(xyz, out);
    ball_query_kernel<<<(NB * NP) / 8, 256>>>(xyz);
    transpose_feat_kernel<<<dim3(NN / 32, CIN / 32, NB), dim3(32, 8)>>>(feat);
    pad_w1_kernel<<<64, KP1>>>(W1);
    build_g_kernel<<<NROWS, KP1>>>(xyz);
    gemm_bn_relu<1><<<dim3(NROWS / 64, 1), 256>>>(W1, g1, b1);
    gemm_bn_relu<2><<<dim3(NROWS / 64, 2), 256>>>(W2, g2, b2);
    gemm_bn_relu<3><<<dim3(NROWS / 64, 4), 256>>>(W3, g3, b3);
    maxpool_kernel<<<NB * NP, CD>>>();
    // attention path (device-gated on alpha[0] != 0; alpha==0 in this dataset)
    squeeze_kernel<<<NB, CD>>>(alpha);
    excite_kernel<<<NB, CD>>>(We1, We2, alpha);
    qk_kernel<<<dim3(CD, NB, 2), CD>>>(Wq, gq, bq, Wk, gk, bk, alpha);
    sim_softmax_kernel<<<dim3(CD, NB), CD>>>(alpha);
    final_write_kernel<<<dim3(NP / 256, CD, NB), 256>>>(out, alpha);
}

// round 15
// speedup vs baseline: 2.5504x; 1.0622x over previous
#include <cuda_runtime.h>
#include <cuda_bf16.h>
#include <cooperative_groups.h>
#include <math.h>
#include <stdint.h>

namespace cg = cooperative_groups;

// ---------------- problem constants ----------------
#define NB 2
#define NN 16384
#define CIN 64
#define NP 2048
#define NS 32
#define CD 256
#define KP1 80                  // 3+64=67 padded to 80
#define NROWS (NB*NP*NS)        // 131072

// FPS cluster config
#define FT 256                  // threads per FPS CTA
#define NW (FT / 32)            // 8 warps
#define CLS 8                   // cluster size (CTAs per batch)
#define SHARD (NN / CLS)        // 2048 points owned per CTA
#define SLOTS (SHARD / FT)      // 8 slots per thread (register-resident coords)
#define NKEY (NW * CLS)         // 64 candidate keys per iteration
#define FPS_SMEM (NN * 12)      // full copy: float2 xy + float z = 196608 B

// ---------------- scratch (device globals; no allocation allowed) ----------------
__device__ alignas(256) int   g_samp[NB * NP];
__device__ alignas(256) float g_newxyz[NB * NP * 3];
__device__ alignas(256) int   g_nn[NROWS];
__device__ alignas(256) float g_featT[(size_t)NB * NN * CIN];
__device__ alignas(256) float g_Wp1[64 * KP1];
__device__ alignas(256) float g_G[(size_t)NROWS * KP1];
__device__ alignas(256) float g_H1[(size_t)NROWS * 64];
__device__ alignas(256) float g_H2[(size_t)NROWS * 128];
__device__ alignas(256) float g_xh[(size_t)NB * NP * CD];   // (b,p,c)
__device__ alignas(256) float g_qt[(size_t)NB * CD * CD];
__device__ alignas(256) float g_kt[(size_t)NB * CD * CD];
__device__ alignas(256) float g_aff[(size_t)NB * CD * CD];
__device__ alignas(256) float g_s[NB * CD];
__device__ alignas(256) float g_e[NB * CD];

// ---------------- small PTX helpers ----------------
__device__ __forceinline__ uint32_t smem_u32(const void* p) {
    uint32_t a;
    asm("{ .reg .u64 t; cvta.to.shared.u64 t, %1; cvt.u32.u64 %0, t; }" : "=r"(a) : "l"(p));
    return a;
}
__device__ __forceinline__ uint32_t mapa_u32(uint32_t laddr, uint32_t rank) {
    uint32_t r;
    asm("mapa.shared::cluster.u32 %0, %1, %2;" : "=r"(r) : "r"(laddr), "r"(rank));
    return r;
}
__device__ __forceinline__ void mbar_init(uint32_t mbar, uint32_t cnt) {
    asm volatile("mbarrier.init.shared.b64 [%0], %1;" :: "r"(mbar), "r"(cnt) : "memory");
}
__device__ __forceinline__ void mbar_expect_tx(uint32_t mbar, uint32_t bytes) {
    asm volatile("mbarrier.arrive.expect_tx.shared.b64 _, [%0], %1;"
                 :: "r"(mbar), "r"(bytes) : "memory");
}
__device__ __forceinline__ void st_async_cluster_u64(uint32_t raddr, unsigned long long v,
                                                     uint32_t rmbar) {
    asm volatile("st.async.shared::cluster.mbarrier::complete_tx::bytes.b64 [%0], %1, [%2];"
                 :: "r"(raddr), "l"(v), "r"(rmbar) : "memory");
}
__device__ __forceinline__ void mbar_wait_parity(uint32_t mbar, uint32_t parity) {
    uint32_t done;
    asm volatile(
        "{\n\t.reg .pred p;\n\t"
        "mbarrier.try_wait.parity.acquire.cta.shared::cta.b64 p, [%1], %2;\n\t"
        "selp.b32 %0, 1, 0, p;\n\t}"
        : "=r"(done) : "r"(mbar), "r"(parity) : "memory");
    if (!done) {
        asm volatile(
            "{\n\t.reg .pred P1;\n\t"
            "WL_%=:\n\t"
            "mbarrier.try_wait.parity.acquire.cta.shared::cta.b64 P1, [%0], %1, 0x989680;\n\t"
            "@P1 bra.uni WD_%=;\n\t"
            "bra.uni WL_%=;\n\t"
            "WD_%=:\n\t}"
            :: "r"(mbar), "r"(parity) : "memory");
    }
}

// ================= FPS (cluster-distributed, per-warp direct push) ================
// 8 CTAs per batch; own-shard coordinates in REGISTERS (8 pts/thread); full SMEM
// copy only for winner-coordinate lookup. Per iteration every WARP reduces its
// 256 points to one packed key (dist_bits<<32 | ~index) with REDUX, then pushes
// it directly to all 8 CTAs' cand slot [rank*8+wid] via st.async+complete_tx
// (no block barrier, no block reduce). Receivers wait for 64 keys (512 B tx) on
// a parity-indexed mbarrier pair and reduce the 64 keys with the split-hi/lo
// REDUX trick (max dist, ties -> smallest index: exact jnp.argmax). WAR reuse of
// a cand buffer is transitively ordered: a warp sends iter i+1 only after it
// read all 64 slots of buffer (i&1) at iter i.
extern __shared__ unsigned char fps_sm[];

__global__ void __cluster_dims__(CLS, 1, 1) __launch_bounds__(FT, 1)
fps_cluster_kernel(const float* __restrict__ xyz) {
    float2* xy = (float2*)fps_sm;
    float*  zz = (float*)(fps_sm + (size_t)NN * sizeof(float2));
    __shared__ alignas(16) unsigned long long cand[2][NKEY];
    __shared__ alignas(8)  unsigned long long mbar[2];

    cg::cluster_group cluster = cg::this_cluster();
    const unsigned rank = cluster.block_rank();
    const int b = blockIdx.x / CLS;
    const int t = threadIdx.x;
    const int lane = t & 31, wid = t >> 5;
    const int base = rank * SHARD;

    // full local copy of this batch's points (for winner-coordinate lookup)
    const float* xb = xyz + (size_t)b * NN * 3;
    for (int p = t; p < NN; p += FT) {
        xy[p] = make_float2(xb[p * 3 + 0], xb[p * 3 + 1]);
        zz[p] = xb[p * 3 + 2];
    }

    uint32_t mb0 = smem_u32(&mbar[0]);
    uint32_t mb1 = smem_u32(&mbar[1]);
    if (t == 0) {
        mbar_init(mb0, 1);
        mbar_init(mb1, 1);
        if (rank == 0) g_samp[b * NP + 0] = 0;
    }
    // publish smem copy + mbarrier init to the cluster (one-time)
    cluster.sync();

    // own-shard coordinates in registers
    float px[SLOTS], py[SLOTS], pz[SLOTS], mind[SLOTS];
#pragma unroll
    for (int s = 0; s < SLOTS; s++) {
        int p = base + t + s * FT;
        float2 a = xy[p];
        px[s] = a.x; py[s] = a.y; pz[s] = zz[p];
        mind[s] = 3.4e38f;
    }

    // per-warp remote slot addresses (peer = lane, slot = rank*NW + wid)
    uint32_t rc0 = 0, rc1 = 0, rm0 = 0, rm1 = 0;
    if (lane < CLS) {
        uint32_t lc0 = smem_u32(&cand[0][rank * NW + wid]);
        uint32_t lc1 = smem_u32(&cand[1][rank * NW + wid]);
        rc0 = mapa_u32(lc0, lane);
        rc1 = mapa_u32(lc1, lane);
        rm0 = mapa_u32(mb0, lane);
        rm1 = mapa_u32(mb1, lane);
    }

    int cur = 0;
    for (int i = 1; i < NP; i++) {
        float2 cxy = xy[cur];
        float  cz  = zz[cur];
        float bestm = -1.0f; unsigned bidx = 0;
#pragma unroll
        for (int s = 0; s < SLOTS; s++) {
            float dx = px[s] - cxy.x, dy = py[s] - cxy.y, dz = pz[s] - cz;
            float d = dx * dx + dy * dy + dz * dz;     // identical expr to R11-R14
            float m = fminf(mind[s], d);
            mind[s] = m;
            if (m > bestm) { bestm = m; bidx = (unsigned)(base + t + s * FT); }
        }
        // warp reduce: max dist bits, then min index among matching lanes
        unsigned mb = __float_as_uint(bestm);          // bestm >= 0 -> bit-ordered
        unsigned wmax = __reduce_max_sync(0xffffffffu, mb);
        unsigned cidx = (mb == wmax) ? bidx : 0xffffffffu;
        unsigned widx = __reduce_min_sync(0xffffffffu, cidx);
        unsigned long long key =
            ((unsigned long long)wmax << 32) | (unsigned)(~widx);

        const int bi = (i - 1) & 1;                  // buffer / mbarrier index
        const uint32_t ph = ((unsigned)(i - 1) >> 1) & 1u;  // phase parity of mbar[bi]
        if (t == 0) mbar_expect_tx(bi ? mb1 : mb0, NKEY * 8u);
        if (lane < CLS)
            st_async_cluster_u64(bi ? rc1 : rc0, key, bi ? rm1 : rm0);

        // all threads wait for all 64 candidates to land locally
        mbar_wait_parity(bi ? mb1 : mb0, ph);
        unsigned long long k0 = cand[bi][lane];
        unsigned long long k1 = cand[bi][lane + 32];
        unsigned long long k = (k1 > k0) ? k1 : k0;
        unsigned hi = (unsigned)(k >> 32), lo = (unsigned)k;
        unsigned mhi = __reduce_max_sync(0xffffffffu, hi);
        unsigned mlo = __reduce_max_sync(0xffffffffu, (hi == mhi) ? lo : 0u);
        cur = (int)(~mlo);
        if (rank == 0 && t == 0) g_samp[b * NP + i] = cur;
    }
}

// ================= gather new_xyz (also writes first section of d_out) ============
__global__ void gather_new_kernel(const float* __restrict__ xyz, float* __restrict__ out) {
    int i = blockIdx.x * blockDim.x + threadIdx.x;
    if (i >= NB * NP * 3) return;
    int bp = i / 3, k = i - bp * 3;
    int b = bp / NP;
    int idx = g_samp[bp];
    float v = xyz[((size_t)b * NN + idx) * 3 + k];
    out[i] = v;
    g_newxyz[i] = v;
}

// ================= ball query: first NS in-range by ascending index, pad w/ first hit
__global__ void ball_query_kernel(const float* __restrict__ xyz) {
    int gw = (blockIdx.x * blockDim.x + threadIdx.x) >> 5;
    int lane = threadIdx.x & 31;
    if (gw >= NB * NP) return;
    int b = gw / NP;
    float cx = g_newxyz[gw * 3 + 0], cy = g_newxyz[gw * 3 + 1], cz = g_newxyz[gw * 3 + 2];
    const float* xb = xyz + (size_t)b * NN * 3;
    int base = gw * NS;
    int cnt = 0, first = -1;
    const float rr = 0.8f * 0.8f;
    for (int c0 = 0; c0 < NN; c0 += 32) {
        int j = c0 + lane;
        float dx = cx - xb[j * 3 + 0];
        float dy = cy - xb[j * 3 + 1];
        float dz = cz - xb[j * 3 + 2];
        float d = dx * dx + dy * dy + dz * dz;
        bool in = d < rr;
        unsigned m = __ballot_sync(0xffffffffu, in);
        if (first < 0 && m) first = c0 + (__ffs(m) - 1);
        if (in) {
            int pos = cnt + __popc(m & ((1u << lane) - 1u));
            if (pos < NS) g_nn[base + pos] = j;
        }
        cnt += __popc(m);
        if (cnt >= NS) break;
    }
    if (cnt < NS) {
        for (int k = cnt + lane; k < NS; k += 32) g_nn[base + k] = first;
    }
}

// ================= transpose features (B,C,N) -> (B,N,C) ==================
__global__ void transpose_feat_kernel(const float* __restrict__ f) {
    __shared__ float tile[32][33];
    int b = blockIdx.z;
    int n0 = blockIdx.x * 32, c0 = blockIdx.y * 32;
#pragma unroll
    for (int r = 0; r < 4; r++) {
        int c = c0 + threadIdx.y + r * 8;
        tile[threadIdx.y + r * 8][threadIdx.x] =
            f[((size_t)b * CIN + c) * NN + n0 + threadIdx.x];
    }
    __syncthreads();
#pragma unroll
    for (int r = 0; r < 4; r++) {
        int n = n0 + threadIdx.y + r * 8;
        g_featT[((size_t)b * NN + n) * CIN + c0 + threadIdx.x] =
            tile[threadIdx.x][threadIdx.y + r * 8];
    }
}

// ================= pad W1 (64x67) -> (64x80) ==================
__global__ void pad_w1_kernel(const float* __restrict__ W1) {
    int o = blockIdx.x, k = threadIdx.x;
    g_Wp1[o * KP1 + k] = (k < 67) ? W1[o * 67 + k] : 0.0f;
}

// ================= build grouped matrix G (NROWS x 80) ==================
__global__ void build_g_kernel(const float* __restrict__ xyz) {
    int row = blockIdx.x;
    int k = threadIdx.x;            // 0..79
    int b = row / (NP * NS);
    int rem = row - b * (NP * NS);
    int p = rem / NS;
    int nn = g_nn[row];
    float v = 0.0f;
    if (k < 3)       v = xyz[((size_t)b * NN + nn) * 3 + k] - g_newxyz[(b * NP + p) * 3 + k];
    else if (k < 67) v = g_featT[((size_t)b * NN + nn) * CIN + (k - 3)];
    g_G[(size_t)row * KP1 + k] = v;
}

// ================= GEMM + BN(eval) + ReLU (layer 3 fuses the 32-way maxpool) ======
// C[m,n] = relu( (sum_k A[m,k]*W[n,k]) * g[n]/sqrt(1+eps) + b[n] )
template<int LAYER>
__global__ void __launch_bounds__(256) gemm_bn_relu(const float* __restrict__ W,
                                                    const float* __restrict__ gs,
                                                    const float* __restrict__ bt) {
    constexpr int K = (LAYER == 1) ? KP1 : ((LAYER == 2) ? 64 : 128);
    constexpr int N = (LAYER == 1) ? 64 : ((LAYER == 2) ? 128 : 256);
    const float* A = (LAYER == 1) ? (const float*)g_G
                   : (LAYER == 2) ? (const float*)g_H1 : (const float*)g_H2;
    float* C = (LAYER == 1) ? (float*)g_H1 : (float*)g_H2;   // unused for LAYER==3
    const float* Wp = (LAYER == 1) ? (const float*)g_Wp1 : W;

    __shared__ float As[16][65];
    __shared__ float Ws[16][65];
    __shared__ int red[2][64];      // LAYER==3: maxpool accum (relu >= 0 -> int order)
    int tid = threadIdx.x;
    int tx = tid & 15, ty = tid >> 4;
    int m0 = blockIdx.x * 64, n0 = blockIdx.y * 64;
    int lm = tid >> 2, lk = (tid & 3) * 4;
    const float* Ag = A  + (size_t)(m0 + lm) * K + lk;
    const float* Wg = Wp + (size_t)(n0 + lm) * K + lk;
    float acc[4][4] = {};

    if (LAYER == 3 && tid < 128) red[tid >> 6][tid & 63] = 0;

    for (int kt = 0; kt < K; kt += 16) {
        float4 av = *(const float4*)(Ag + kt);
        float4 wv = *(const float4*)(Wg + kt);
        As[lk + 0][lm] = av.x; As[lk + 1][lm] = av.y; As[lk + 2][lm] = av.z; As[lk + 3][lm] = av.w;
        Ws[lk + 0][lm] = wv.x; Ws[lk + 1][lm] = wv.y; Ws[lk + 2][lm] = wv.z; Ws[lk + 3][lm] = wv.w;
        __syncthreads();
#pragma unroll
        for (int k = 0; k < 16; k++) {
            float a[4], bb[4];
#pragma unroll
            for (int i2 = 0; i2 < 4; i2++) a[i2] = As[k][ty * 4 + i2];
#pragma unroll
            for (int j = 0; j < 4; j++) bb[j] = Ws[k][tx * 4 + j];
#pragma unroll
            for (int i2 = 0; i2 < 4; i2++)
#pragma unroll
                for (int j = 0; j < 4; j++) acc[i2][j] = fmaf(a[i2], bb[j], acc[i2][j]);
        }
        __syncthreads();
    }
#pragma unroll
    for (int j = 0; j < 4; j++) {
        int n = n0 + tx * 4 + j;
        float s = gs[n] / sqrtf(1.0f + 1e-5f);
        float bb = bt[n];
        if (LAYER != 3) {
#pragma unroll
            for (int i2 = 0; i2 < 4; i2++) {
                int m = m0 + ty * 4 + i2;
                C[(size_t)m * N + n] = fmaxf(fmaf(acc[i2][j], s, bb), 0.0f);
            }
        } else {
            // rows ty*4..ty*4+3 all lie in group g = ty>>3 (NS=32 | 64-row tile)
            float v = fmaxf(fmaf(acc[0][j], s, bb), 0.0f);
#pragma unroll
            for (int i2 = 1; i2 < 4; i2++)
                v = fmaxf(v, fmaxf(fmaf(acc[i2][j], s, bb), 0.0f));
            atomicMax(&red[ty >> 3][tx * 4 + j], __float_as_int(v));
        }
    }
    if (LAYER == 3) {
        __syncthreads();
        if (tid < 128) {
            int g = tid >> 6, nn = tid & 63;
            int bp = m0 / 32 + g;                       // group row index (b*NP+p)
            g_xh[(size_t)bp * CD + n0 + nn] = __int_as_float(red[g][nn]);
        }
    }
}

// ================= attention path (gated on alpha != 0) ==================
__global__ void squeeze_kernel(const float* __restrict__ alpha) {
    if (alpha[0] == 0.0f) return;
    int c = threadIdx.x, b = blockIdx.x;
    float m = -3.4e38f;
    for (int p = 0; p < NP; p++)
        m = fmaxf(m, g_xh[((size_t)b * NP + p) * CD + c]);
    g_s[b * CD + c] = m;
}

__global__ void excite_kernel(const float* __restrict__ We1, const float* __restrict__ We2,
                              const float* __restrict__ alpha) {
    if (alpha[0] == 0.0f) return;
    int b = blockIdx.x, t = threadIdx.x;
    __shared__ float h[32];
    if (t < 32) {
        float a = 0.0f;
        for (int i = 0; i < CD; i++) a += We1[t * CD + i] * g_s[b * CD + i];
        h[t] = fmaxf(a, 0.0f);
    }
    __syncthreads();
    float a = 0.0f;
    for (int j = 0; j < 32; j++) a += We2[t * 32 + j] * h[j];
    g_e[b * CD + t] = 1.0f / (1.0f + expf(-a));
}

__global__ void qk_kernel(const float* __restrict__ Wq, const float* __restrict__ gq,
                          const float* __restrict__ bq, const float* __restrict__ Wk,
                          const float* __restrict__ gk, const float* __restrict__ bk,
                          const float* __restrict__ alpha) {
    if (alpha[0] == 0.0f) return;
    int c = threadIdx.x, o = blockIdx.x, b = blockIdx.y, which = blockIdx.z;
    const float* W  = which ? Wk : Wq;
    const float* g  = which ? gk : gq;
    const float* bt = which ? bk : bq;
    float acc = 0.0f;
    const float* xb = g_xh + (size_t)b * NP * CD + c;
    const float* wr = W + (size_t)o * NP;
    for (int p = 0; p < NP; p++) acc += wr[p] * xb[(size_t)p * CD];
    float s = g[o] / sqrtf(1.0f + 1e-5f);
    float v = fmaxf(acc * s + bt[o], 0.0f);
    float* dst = which ? g_kt : g_qt;
    dst[((size_t)b * CD + o) * CD + c] = v;
}

__global__ void sim_softmax_kernel(const float* __restrict__ alpha) {
    if (alpha[0] == 0.0f) return;
    int c = blockIdx.x, b = blockIdx.y, d = threadIdx.x;
    __shared__ float sb[32];
    int lane = d & 31, wid = d >> 5;
    const float* kb = g_kt + (size_t)b * CD * CD;
    const float* qb = g_qt + (size_t)b * CD * CD;
    float sim = 0.0f;
    for (int q = 0; q < CD; q++) sim += kb[q * CD + c] * qb[q * CD + d];
    // softmax(rowmax - sim) == exp(rowmin - sim)/sum(exp(rowmin - sim))
    float mn = sim;
#pragma unroll
    for (int o = 16; o; o >>= 1) mn = fminf(mn, __shfl_xor_sync(0xffffffffu, mn, o));
    if (lane == 0) sb[wid] = mn;
    __syncthreads();
    float Mn = sb[0];
    for (int w = 1; w < 8; w++) Mn = fminf(Mn, sb[w]);
    __syncthreads();
    float num = expf(Mn - sim);
    float sm = num;
#pragma unroll
    for (int o = 16; o; o >>= 1) sm += __shfl_xor_sync(0xffffffffu, sm, o);
    if (lane == 0) sb[wid] = sm;
    __syncthreads();
    float S = 0.0f;
    for (int w = 0; w < 8; w++) S += sb[w];
    g_aff[((size_t)b * CD + c) * CD + d] = num / S;
}

// ================= final write: out[b,c,p] = alpha*(aff@v)[c,p] + x[c,p] ========
__global__ void final_write_kernel(float* __restrict__ out, const float* __restrict__ alpha) {
    int p = blockIdx.x * blockDim.x + threadIdx.x;
    int c = blockIdx.y, b = blockIdx.z;
    float a = alpha[0];
    float base = g_xh[((size_t)b * NP + p) * CD + c];
    float res = base;
    if (a != 0.0f) {
        const float* affr = g_aff + ((size_t)b * CD + c) * CD;
        const float* xhp  = g_xh + ((size_t)b * NP + p) * CD;
        const float* eb   = g_e + b * CD;
        float acc = 0.0f;
        for (int d = 0; d < CD; d++) acc += affr[d] * xhp[d] * eb[d];
        res = a * acc + base;
    }
    out[NB * NP * 3 + ((size_t)b * CD + c) * NP + p] = res;
}

// ================= host launcher ==================
extern "C" void kernel_launch(void* const* d_in, const int* in_sizes, int n_in,
                              void* d_out, int out_size) {
    const float* xyz  = (const float*)d_in[0];
    const float* feat = (const float*)d_in[1];
    const float* W1 = (const float*)d_in[2];
    const float* g1 = (const float*)d_in[3];
    const float* b1 = (const float*)d_in[4];
    const float* W2 = (const float*)d_in[5];
    const float* g2 = (const float*)d_in[6];
    const float* b2 = (const float*)d_in[7];
    const float* W3 = (const float*)d_in[8];
    const float* g3 = (const float*)d_in[9];
    const float* b3 = (const float*)d_in[10];
    const float* Wq = (const float*)d_in[11];
    const float* gq = (const float*)d_in[12];
    const float* bq = (const float*)d_in[13];
    const float* Wk = (const float*)d_in[14];
    const float* gk = (const float*)d_in[15];
    const float* bk = (const float*)d_in[16];
    const float* We1 = (const float*)d_in[17];
    const float* We2 = (const float*)d_in[18];
    const float* alpha = (const float*)d_in[19];
    float* out = (float*)d_out;

    cudaFuncSetAttribute(fps_cluster_kernel,
                         cudaFuncAttributeMaxDynamicSharedMemorySize, FPS_SMEM);

    fps_cluster_kernel<<<NB * CLS, FT, FPS_SMEM>>>(xyz);
    gather_new_kernel<<<(NB * NP * 3 + 255) / 256, 256>>>(xyz, out);
    ball_query_kernel<<<(NB * NP) / 8, 256>>>(xyz);
    transpose_feat_kernel<<<dim3(NN / 32, CIN / 32, NB), dim3(32, 8)>>>(feat);
    pad_w1_kernel<<<64, KP1>>>(W1);
    build_g_kernel<<<NROWS, KP1>>>(xyz);
    gemm_bn_relu<1><<<dim3(NROWS / 64, 1), 256>>>(W1, g1, b1);
    gemm_bn_relu<2><<<dim3(NROWS / 64, 2), 256>>>(W2, g2, b2);
    gemm_bn_relu<3><<<dim3(NROWS / 64, 4), 256>>>(W3, g3, b3);   // fused maxpool -> g_xh
    // attention path (device-gated on alpha[0] != 0; alpha==0 in this dataset)
    squeeze_kernel<<<NB, CD>>>(alpha);
    excite_kernel<<<NB, CD>>>(We1, We2, alpha);
    qk_kernel<<<dim3(CD, NB, 2), CD>>>(Wq, gq, bq, Wk, gk, bk, alpha);
    sim_softmax_kernel<<<dim3(CD, NB), CD>>>(alpha);
    final_write_kernel<<<dim3(NP / 256, CD, NB), 256>>>(out, alpha);
}

// round 16
// speedup vs baseline: 2.9012x; 1.1376x over previous
#include <cuda_runtime.h>
#include <cuda_bf16.h>
#include <cooperative_groups.h>
#include <math.h>
#include <stdint.h>

namespace cg = cooperative_groups;

// ---------------- problem constants ----------------
#define NB 2
#define NN 16384
#define CIN 64
#define NP 2048
#define NS 32
#define CD 256
#define KP1 80                  // 3+64=67 padded to 80
#define NROWS (NB*NP*NS)        // 131072

// FPS cluster config
#define FT 256                  // threads per FPS CTA
#define NW (FT / 32)            // 8 warps
#define CLS 8                   // cluster size (CTAs per batch)
#define SHARD (NN / CLS)        // 2048 points owned per CTA
#define SLOTS (SHARD / FT)      // 8 slots per thread (register-resident coords)
#define NKEY (NW * CLS)         // 64 candidate keys per iteration
#define FPS_SMEM (NN * 12)      // full copy: float2 xy + float z = 196608 B

// ---------------- scratch (device globals; no allocation allowed) ----------------
__device__ alignas(256) int   g_samp[NB * NP];
__device__ alignas(256) float g_newxyz[NB * NP * 3];
__device__ alignas(256) int   g_nn[NROWS];
__device__ alignas(256) float g_featT[(size_t)NB * NN * CIN];
__device__ alignas(256) float g_Wp1[64 * KP1];
__device__ alignas(256) float g_G[(size_t)NROWS * KP1];
__device__ alignas(256) float g_H1[(size_t)NROWS * 64];
__device__ alignas(256) float g_H2[(size_t)NROWS * 128];
__device__ alignas(256) float g_xh[(size_t)NB * NP * CD];   // (b,p,c)
__device__ alignas(256) float g_qt[(size_t)NB * CD * CD];
__device__ alignas(256) float g_kt[(size_t)NB * CD * CD];
__device__ alignas(256) float g_aff[(size_t)NB * CD * CD];
__device__ alignas(256) float g_s[NB * CD];
__device__ alignas(256) float g_e[NB * CD];

// ---------------- small PTX helpers ----------------
__device__ __forceinline__ uint32_t smem_u32(const void* p) {
    uint32_t a;
    asm("{ .reg .u64 t; cvta.to.shared.u64 t, %1; cvt.u32.u64 %0, t; }" : "=r"(a) : "l"(p));
    return a;
}
__device__ __forceinline__ uint32_t mapa_u32(uint32_t laddr, uint32_t rank) {
    uint32_t r;
    asm("mapa.shared::cluster.u32 %0, %1, %2;" : "=r"(r) : "r"(laddr), "r"(rank));
    return r;
}
__device__ __forceinline__ void mbar_init(uint32_t mbar, uint32_t cnt) {
    asm volatile("mbarrier.init.shared.b64 [%0], %1;" :: "r"(mbar), "r"(cnt) : "memory");
}
__device__ __forceinline__ void mbar_expect_tx(uint32_t mbar, uint32_t bytes) {
    asm volatile("mbarrier.arrive.expect_tx.shared.b64 _, [%0], %1;"
                 :: "r"(mbar), "r"(bytes) : "memory");
}
__device__ __forceinline__ void st_async_cluster_u64(uint32_t raddr, unsigned long long v,
                                                     uint32_t rmbar) {
    asm volatile("st.async.shared::cluster.mbarrier::complete_tx::bytes.b64 [%0], %1, [%2];"
                 :: "r"(raddr), "l"(v), "r"(rmbar) : "memory");
}
__device__ __forceinline__ void mbar_wait_parity(uint32_t mbar, uint32_t parity) {
    uint32_t done;
    asm volatile(
        "{\n\t.reg .pred p;\n\t"
        "mbarrier.try_wait.parity.acquire.cta.shared::cta.b64 p, [%1], %2;\n\t"
        "selp.b32 %0, 1, 0, p;\n\t}"
        : "=r"(done) : "r"(mbar), "r"(parity) : "memory");
    if (!done) {
        asm volatile(
            "{\n\t.reg .pred P1;\n\t"
            "WL_%=:\n\t"
            "mbarrier.try_wait.parity.acquire.cta.shared::cta.b64 P1, [%0], %1, 0x989680;\n\t"
            "@P1 bra.uni WD_%=;\n\t"
            "bra.uni WL_%=;\n\t"
            "WD_%=:\n\t}"
            :: "r"(mbar), "r"(parity) : "memory");
    }
}

// tf32 split: x = hi + lo with both tf32-representable; dropped lo*lo <= 2^-24 rel.
__device__ __forceinline__ void split2(float x, uint32_t& hi, uint32_t& lo) {
    uint32_t h;
    asm("cvt.rna.tf32.f32 %0, %1;" : "=r"(h) : "f"(x));
    float r = x - __uint_as_float(h);
    uint32_t l;
    asm("cvt.rna.tf32.f32 %0, %1;" : "=r"(l) : "f"(r));
    hi = h; lo = l;
}
__device__ __forceinline__ void mma_tf32(float* c, const uint32_t* a, const uint32_t* b) {
    asm volatile(
        "mma.sync.aligned.m16n8k8.row.col.f32.tf32.tf32.f32 "
        "{%0,%1,%2,%3}, {%4,%5,%6,%7}, {%8,%9}, {%0,%1,%2,%3};"
        : "+f"(c[0]), "+f"(c[1]), "+f"(c[2]), "+f"(c[3])
        : "r"(a[0]), "r"(a[1]), "r"(a[2]), "r"(a[3]), "r"(b[0]), "r"(b[1]));
}

// ================= FPS (cluster-distributed, per-warp direct push) ================
extern __shared__ unsigned char fps_sm[];

__global__ void __cluster_dims__(CLS, 1, 1) __launch_bounds__(FT, 1)
fps_cluster_kernel(const float* __restrict__ xyz) {
    float2* xy = (float2*)fps_sm;
    float*  zz = (float*)(fps_sm + (size_t)NN * sizeof(float2));
    __shared__ alignas(16) unsigned long long cand[2][NKEY];
    __shared__ alignas(8)  unsigned long long mbar[2];

    cg::cluster_group cluster = cg::this_cluster();
    const unsigned rank = cluster.block_rank();
    const int b = blockIdx.x / CLS;
    const int t = threadIdx.x;
    const int lane = t & 31, wid = t >> 5;
    const int base = rank * SHARD;

    const float* xb = xyz + (size_t)b * NN * 3;
    for (int p = t; p < NN; p += FT) {
        xy[p] = make_float2(xb[p * 3 + 0], xb[p * 3 + 1]);
        zz[p] = xb[p * 3 + 2];
    }

    uint32_t mb0 = smem_u32(&mbar[0]);
    uint32_t mb1 = smem_u32(&mbar[1]);
    if (t == 0) {
        mbar_init(mb0, 1);
        mbar_init(mb1, 1);
        if (rank == 0) g_samp[b * NP + 0] = 0;
    }
    cluster.sync();

    float px[SLOTS], py[SLOTS], pz[SLOTS], mind[SLOTS];
#pragma unroll
    for (int s = 0; s < SLOTS; s++) {
        int p = base + t + s * FT;
        float2 a = xy[p];
        px[s] = a.x; py[s] = a.y; pz[s] = zz[p];
        mind[s] = 3.4e38f;
    }

    uint32_t rc0 = 0, rc1 = 0, rm0 = 0, rm1 = 0;
    if (lane < CLS) {
        uint32_t lc0 = smem_u32(&cand[0][rank * NW + wid]);
        uint32_t lc1 = smem_u32(&cand[1][rank * NW + wid]);
        rc0 = mapa_u32(lc0, lane);
        rc1 = mapa_u32(lc1, lane);
        rm0 = mapa_u32(mb0, lane);
        rm1 = mapa_u32(mb1, lane);
    }

    int cur = 0;
    for (int i = 1; i < NP; i++) {
        float2 cxy = xy[cur];
        float  cz  = zz[cur];
        float bestm = -1.0f; unsigned bidx = 0;
#pragma unroll
        for (int s = 0; s < SLOTS; s++) {
            float dx = px[s] - cxy.x, dy = py[s] - cxy.y, dz = pz[s] - cz;
            float d = dx * dx + dy * dy + dz * dz;     // identical expr to R11-R15
            float m = fminf(mind[s], d);
            mind[s] = m;
            if (m > bestm) { bestm = m; bidx = (unsigned)(base + t + s * FT); }
        }
        unsigned mb = __float_as_uint(bestm);
        unsigned wmax = __reduce_max_sync(0xffffffffu, mb);
        unsigned cidx = (mb == wmax) ? bidx : 0xffffffffu;
        unsigned widx = __reduce_min_sync(0xffffffffu, cidx);
        unsigned long long key =
            ((unsigned long long)wmax << 32) | (unsigned)(~widx);

        const int bi = (i - 1) & 1;
        const uint32_t ph = ((unsigned)(i - 1) >> 1) & 1u;
        if (t == 0) mbar_expect_tx(bi ? mb1 : mb0, NKEY * 8u);
        if (lane < CLS)
            st_async_cluster_u64(bi ? rc1 : rc0, key, bi ? rm1 : rm0);

        mbar_wait_parity(bi ? mb1 : mb0, ph);
        unsigned long long k0 = cand[bi][lane];
        unsigned long long k1 = cand[bi][lane + 32];
        unsigned long long k = (k1 > k0) ? k1 : k0;
        unsigned hi = (unsigned)(k >> 32), lo = (unsigned)k;
        unsigned mhi = __reduce_max_sync(0xffffffffu, hi);
        unsigned mlo = __reduce_max_sync(0xffffffffu, (hi == mhi) ? lo : 0u);
        cur = (int)(~mlo);
        if (rank == 0 && t == 0) g_samp[b * NP + i] = cur;
    }
}

// ================= gather new_xyz (also writes first section of d_out) ============
__global__ void gather_new_kernel(const float* __restrict__ xyz, float* __restrict__ out) {
    int i = blockIdx.x * blockDim.x + threadIdx.x;
    if (i >= NB * NP * 3) return;
    int bp = i / 3, k = i - bp * 3;
    int b = bp / NP;
    int idx = g_samp[bp];
    float v = xyz[((size_t)b * NN + idx) * 3 + k];
    out[i] = v;
    g_newxyz[i] = v;
}

// ================= ball query =================
__global__ void ball_query_kernel(const float* __restrict__ xyz) {
    int gw = (blockIdx.x * blockDim.x + threadIdx.x) >> 5;
    int lane = threadIdx.x & 31;
    if (gw >= NB * NP) return;
    int b = gw / NP;
    float cx = g_newxyz[gw * 3 + 0], cy = g_newxyz[gw * 3 + 1], cz = g_newxyz[gw * 3 + 2];
    const float* xb = xyz + (size_t)b * NN * 3;
    int base = gw * NS;
    int cnt = 0, first = -1;
    const float rr = 0.8f * 0.8f;
    for (int c0 = 0; c0 < NN; c0 += 32) {
        int j = c0 + lane;
        float dx = cx - xb[j * 3 + 0];
        float dy = cy - xb[j * 3 + 1];
        float dz = cz - xb[j * 3 + 2];
        float d = dx * dx + dy * dy + dz * dz;
        bool in = d < rr;
        unsigned m = __ballot_sync(0xffffffffu, in);
        if (first < 0 && m) first = c0 + (__ffs(m) - 1);
        if (in) {
            int pos = cnt + __popc(m & ((1u << lane) - 1u));
            if (pos < NS) g_nn[base + pos] = j;
        }
        cnt += __popc(m);
        if (cnt >= NS) break;
    }
    if (cnt < NS) {
        for (int k = cnt + lane; k < NS; k += 32) g_nn[base + k] = first;
    }
}

// ================= transpose features (B,C,N) -> (B,N,C) ==================
__global__ void transpose_feat_kernel(const float* __restrict__ f) {
    __shared__ float tile[32][33];
    int b = blockIdx.z;
    int n0 = blockIdx.x * 32, c0 = blockIdx.y * 32;
#pragma unroll
    for (int r = 0; r < 4; r++) {
        int c = c0 + threadIdx.y + r * 8;
        tile[threadIdx.y + r * 8][threadIdx.x] =
            f[((size_t)b * CIN + c) * NN + n0 + threadIdx.x];
    }
    __syncthreads();
#pragma unroll
    for (int r = 0; r < 4; r++) {
        int n = n0 + threadIdx.y + r * 8;
        g_featT[((size_t)b * NN + n) * CIN + c0 + threadIdx.x] =
            tile[threadIdx.x][threadIdx.y + r * 8];
    }
}

// ================= pad W1 (64x67) -> (64x80) ==================
__global__ void pad_w1_kernel(const float* __restrict__ W1) {
    int o = blockIdx.x, k = threadIdx.x;
    g_Wp1[o * KP1 + k] = (k < 67) ? W1[o * 67 + k] : 0.0f;
}

// ================= build grouped matrix G (NROWS x 80) ==================
__global__ void build_g_kernel(const float* __restrict__ xyz) {
    int row = blockIdx.x;
    int k = threadIdx.x;            // 0..79
    int b = row / (NP * NS);
    int rem = row - b * (NP * NS);
    int p = rem / NS;
    int nn = g_nn[row];
    float v = 0.0f;
    if (k < 3)       v = xyz[((size_t)b * NN + nn) * 3 + k] - g_newxyz[(b * NP + p) * 3 + k];
    else if (k < 67) v = g_featT[((size_t)b * NN + nn) * CIN + (k - 3)];
    g_G[(size_t)row * KP1 + k] = v;
}

// ================= tensor-core GEMM (tf32 split-2) + BN + ReLU =====================
// C[m,n] = relu( (sum_k A[m,k]*W[n,k]) * g[n]/sqrt(1+eps) + b[n] )
// 128x64 CTA tile, 8 warps (4m x 2n), warp tile 32x32, k-step 16.
// Smem k-major with pad (As[k][132], Bs[k][68]) -> conflict-free fragment LDS.
// LAYER 3 fuses the 32-way maxpool (row-group == warp_m) via smem atomicMax.
template<int LAYER>
__global__ void __launch_bounds__(256) mma_gemm(const float* __restrict__ W,
                                                const float* __restrict__ gs,
                                                const float* __restrict__ bt) {
    constexpr int K = (LAYER == 1) ? KP1 : ((LAYER == 2) ? 64 : 128);
    constexpr int N = (LAYER == 1) ? 64 : ((LAYER == 2) ? 128 : 256);
    const float* A = (LAYER == 1) ? (const float*)g_G
                   : (LAYER == 2) ? (const float*)g_H1 : (const float*)g_H2;
    float* C = (LAYER == 1) ? (float*)g_H1 : (float*)g_H2;   // unused for LAYER==3
    const float* Wp = (LAYER == 1) ? (const float*)g_Wp1 : W;

    __shared__ float As[16][132];
    __shared__ float Bs[16][68];
    __shared__ int red[4][64];

    int tid = threadIdx.x;
    int lane = tid & 31, wid = tid >> 5;
    int warp_m = wid & 3, warp_n = wid >> 2;
    int gid = lane >> 2, t4 = lane & 3;
    int m0 = blockIdx.x * 128, n0 = blockIdx.y * 64;

    if (LAYER == 3) red[tid >> 6][tid & 63] = 0;

    float acc[2][4][4] = {};

    for (int k0 = 0; k0 < K; k0 += 16) {
        // global loads (A: 128x16, B: 64x16)
        float4 av[2];
#pragma unroll
        for (int j = 0; j < 2; j++) {
            int idx = tid + j * 256;
            int row = idx >> 2, fc = idx & 3;
            av[j] = *(const float4*)(A + (size_t)(m0 + row) * K + k0 + fc * 4);
        }
        int bn = tid >> 2, bfc = tid & 3;
        float4 bv = *(const float4*)(Wp + (size_t)(n0 + bn) * K + k0 + bfc * 4);

        __syncthreads();   // previous k-step's fragment reads complete
#pragma unroll
        for (int j = 0; j < 2; j++) {
            int idx = tid + j * 256;
            int row = idx >> 2, fc = idx & 3;
            As[fc * 4 + 0][row] = av[j].x; As[fc * 4 + 1][row] = av[j].y;
            As[fc * 4 + 2][row] = av[j].z; As[fc * 4 + 3][row] = av[j].w;
        }
        Bs[bfc * 4 + 0][bn] = bv.x; Bs[bfc * 4 + 1][bn] = bv.y;
        Bs[bfc * 4 + 2][bn] = bv.z; Bs[bfc * 4 + 3][bn] = bv.w;
        __syncthreads();

#pragma unroll
        for (int kb = 0; kb < 16; kb += 8) {
            uint32_t bh[4][2], bl[4][2];
#pragma unroll
            for (int nt = 0; nt < 4; nt++) {
                int n = warp_n * 32 + nt * 8 + gid;
                split2(Bs[kb + t4][n],     bh[nt][0], bl[nt][0]);
                split2(Bs[kb + t4 + 4][n], bh[nt][1], bl[nt][1]);
            }
#pragma unroll
            for (int mt = 0; mt < 2; mt++) {
                int m = warp_m * 32 + mt * 16 + gid;
                uint32_t ah[4], al[4];
                split2(As[kb + t4][m],         ah[0], al[0]);
                split2(As[kb + t4][m + 8],     ah[1], al[1]);
                split2(As[kb + t4 + 4][m],     ah[2], al[2]);
                split2(As[kb + t4 + 4][m + 8], ah[3], al[3]);
#pragma unroll
                for (int nt = 0; nt < 4; nt++) {
                    mma_tf32(acc[mt][nt], ah, bh[nt]);
                    mma_tf32(acc[mt][nt], ah, bl[nt]);
                    mma_tf32(acc[mt][nt], al, bh[nt]);
                }
            }
        }
    }

    // epilogue: BN + ReLU (+ fused maxpool for LAYER 3)
    const float inv = 1.0f / sqrtf(1.0f + 1e-5f);
#pragma unroll
    for (int nt = 0; nt < 4; nt++) {
        int col = warp_n * 32 + nt * 8 + t4 * 2;      // local col (even)
        float s0 = gs[n0 + col] * inv,     b0 = bt[n0 + col];
        float s1 = gs[n0 + col + 1] * inv, b1 = bt[n0 + col + 1];
#pragma unroll
        for (int mt = 0; mt < 2; mt++) {
            int row = warp_m * 32 + mt * 16 + gid;
            float v00 = fmaxf(fmaf(acc[mt][nt][0], s0, b0), 0.0f);
            float v01 = fmaxf(fmaf(acc[mt][nt][1], s1, b1), 0.0f);
            float v10 = fmaxf(fmaf(acc[mt][nt][2], s0, b0), 0.0f);
            float v11 = fmaxf(fmaf(acc[mt][nt][3], s1, b1), 0.0f);
            if (LAYER != 3) {
                *(float2*)(C + (size_t)(m0 + row) * N + n0 + col)     = make_float2(v00, v01);
                *(float2*)(C + (size_t)(m0 + row + 8) * N + n0 + col) = make_float2(v10, v11);
            } else {
                atomicMax(&red[warp_m][col],     __float_as_int(fmaxf(v00, v10)));
                atomicMax(&red[warp_m][col + 1], __float_as_int(fmaxf(v01, v11)));
            }
        }
    }
    if (LAYER == 3) {
        __syncthreads();
        int g = tid >> 6, nn = tid & 63;
        int bp = blockIdx.x * 4 + g;                 // group row index (b*NP+p)
        g_xh[(size_t)bp * CD + n0 + nn] = __int_as_float(red[g][nn]);
    }
}

// ================= attention path (gated on alpha != 0) ==================
__global__ void squeeze_kernel(const float* __restrict__ alpha) {
    if (alpha[0] == 0.0f) return;
    int c = threadIdx.x, b = blockIdx.x;
    float m = -3.4e38f;
    for (int p = 0; p < NP; p++)
        m = fmaxf(m, g_xh[((size_t)b * NP + p) * CD + c]);
    g_s[b * CD + c] = m;
}

__global__ void excite_kernel(const float* __restrict__ We1, const float* __restrict__ We2,
                              const float* __restrict__ alpha) {
    if (alpha[0] == 0.0f) return;
    int b = blockIdx.x, t = threadIdx.x;
    __shared__ float h[32];
    if (t < 32) {
        float a = 0.0f;
        for (int i = 0; i < CD; i++) a += We1[t * CD + i] * g_s[b * CD + i];
        h[t] = fmaxf(a, 0.0f);
    }
    __syncthreads();
    float a = 0.0f;
    for (int j = 0; j < 32; j++) a += We2[t * 32 + j] * h[j];
    g_e[b * CD + t] = 1.0f / (1.0f + expf(-a));
}

__global__ void qk_kernel(const float* __restrict__ Wq, const float* __restrict__ gq,
                          const float* __restrict__ bq, const float* __restrict__ Wk,
                          const float* __restrict__ gk, const float* __restrict__ bk,
                          const float* __restrict__ alpha) {
    if (alpha[0] == 0.0f) return;
    int c = threadIdx.x, o = blockIdx.x, b = blockIdx.y, which = blockIdx.z;
    const float* W  = which ? Wk : Wq;
    const float* g  = which ? gk : gq;
    const float* bt = which ? bk : bq;
    float acc = 0.0f;
    const float* xb = g_xh + (size_t)b * NP * CD + c;
    const float* wr = W + (size_t)o * NP;
    for (int p = 0; p < NP; p++) acc += wr[p] * xb[(size_t)p * CD];
    float s = g[o] / sqrtf(1.0f + 1e-5f);
    float v = fmaxf(acc * s + bt[o], 0.0f);
    float* dst = which ? g_kt : g_qt;
    dst[((size_t)b * CD + o) * CD + c] = v;
}

__global__ void sim_softmax_kernel(const float* __restrict__ alpha) {
    if (alpha[0] == 0.0f) return;
    int c = blockIdx.x, b = blockIdx.y, d = threadIdx.x;
    __shared__ float sb[32];
    int lane = d & 31, wid = d >> 5;
    const float* kb = g_kt + (size_t)b * CD * CD;
    const float* qb = g_qt + (size_t)b * CD * CD;
    float sim = 0.0f;
    for (int q = 0; q < CD; q++) sim += kb[q * CD + c] * qb[q * CD + d];
    float mn = sim;
#pragma unroll
    for (int o = 16; o; o >>= 1) mn = fminf(mn, __shfl_xor_sync(0xffffffffu, mn, o));
    if (lane == 0) sb[wid] = mn;
    __syncthreads();
    float Mn = sb[0];
    for (int w = 1; w < 8; w++) Mn = fminf(Mn, sb[w]);
    __syncthreads();
    float num = expf(Mn - sim);
    float sm = num;
#pragma unroll
    for (int o = 16; o; o >>= 1) sm += __shfl_xor_sync(0xffffffffu, sm, o);
    if (lane == 0) sb[wid] = sm;
    __syncthreads();
    float S = 0.0f;
    for (int w = 0; w < 8; w++) S += sb[w];
    g_aff[((size_t)b * CD + c) * CD + d] = num / S;
}

// ================= final write: out[b,c,p] = alpha*(aff@v)[c,p] + x[c,p] ========
__global__ void final_write_kernel(float* __restrict__ out, const float* __restrict__ alpha) {
    int p = blockIdx.x * blockDim.x + threadIdx.x;
    int c = blockIdx.y, b = blockIdx.z;
    float a = alpha[0];
    float base = g_xh[((size_t)b * NP + p) * CD + c];
    float res = base;
    if (a != 0.0f) {
        const float* affr = g_aff + ((size_t)b * CD + c) * CD;
        const float* xhp  = g_xh + ((size_t)b * NP + p) * CD;
        const float* eb   = g_e + b * CD;
        float acc = 0.0f;
        for (int d = 0; d < CD; d++) acc += affr[d] * xhp[d] * eb[d];
        res = a * acc + base;
    }
    out[NB * NP * 3 + ((size_t)b * CD + c) * NP + p] = res;
}

// ================= host launcher ==================
extern "C" void kernel_launch(void* const* d_in, const int* in_sizes, int n_in,
                              void* d_out, int out_size) {
    const float* xyz  = (const float*)d_in[0];
    const float* feat = (const float*)d_in[1];
    const float* W1 = (const float*)d_in[2];
    const float* g1 = (const float*)d_in[3];
    const float* b1 = (const float*)d_in[4];
    const float* W2 = (const float*)d_in[5];
    const float* g2 = (const float*)d_in[6];
    const float* b2 = (const float*)d_in[7];
    const float* W3 = (const float*)d_in[8];
    const float* g3 = (const float*)d_in[9];
    const float* b3 = (const float*)d_in[10];
    const float* Wq = (const float*)d_in[11];
    const float* gq = (const float*)d_in[12];
    const float* bq = (const float*)d_in[13];
    const float* Wk = (const float*)d_in[14];
    const float* gk = (const float*)d_in[15];
    const float* bk = (const float*)d_in[16];
    const float* We1 = (const float*)d_in[17];
    const float* We2 = (const float*)d_in[18];
    const float* alpha = (const float*)d_in[19];
    float* out = (float*)d_out;

    cudaFuncSetAttribute(fps_cluster_kernel,
                         cudaFuncAttributeMaxDynamicSharedMemorySize, FPS_SMEM);

    fps_cluster_kernel<<<NB * CLS, FT, FPS_SMEM>>>(xyz);
    gather_new_kernel<<<(NB * NP * 3 + 255) / 256, 256>>>(xyz, out);
    ball_query_kernel<<<(NB * NP) / 8, 256>>>(xyz);
    transpose_feat_kernel<<<dim3(NN / 32, CIN / 32, NB), dim3(32, 8)>>>(feat);
    pad_w1_kernel<<<64, KP1>>>(W1);
    build_g_kernel<<<NROWS, KP1>>>(xyz);
    mma_gemm<1><<<dim3(NROWS / 128, 1), 256>>>(W1, g1, b1);
    mma_gemm<2><<<dim3(NROWS / 128, 2), 256>>>(W2, g2, b2);
    mma_gemm<3><<<dim3(NROWS / 128, 4), 256>>>(W3, g3, b3);   // fused maxpool -> g_xh
    // attention path (device-gated on alpha[0] != 0; alpha==0 in this dataset)
    squeeze_kernel<<<NB, CD>>>(alpha);
    excite_kernel<<<NB, CD>>>(We1, We2, alpha);
    qk_kernel<<<dim3(CD, NB, 2), CD>>>(Wq, gq, bq, Wk, gk, bk, alpha);
    sim_softmax_kernel<<<dim3(CD, NB), CD>>>(alpha);
    final_write_kernel<<<dim3(NP / 256, CD, NB), 256>>>(out, alpha);
}